// round 4
// baseline (speedup 1.0000x reference)
#include <cuda_runtime.h>
#include <stdint.h>

// ---------------------------------------------------------------------------
// LateralInhibition: per-batch top-k masking (B=8, N=4,194,304, k=419,430).
//
// Fast path (384MB traffic, 3 streams):
//   A: read 128MB, MLP-4. count v>HI per row; stage window candidates
//      (LO<v<=HI, ~36.6K/row); 1024-bin fine hist over window elems only.
//   B: 8 tiny blocks: exact threshold + tie cutoff. Sets g_fail on any
//      assumption violation.
//   W: masked write (read+write 256MB, MLP-4, float-domain compares)
//      + scratch reset for next graph replay.
// Fallback: ONE kernel, 8 blocks, fully general exact select (only runs when
//   g_fail; ~0.5us early-exit otherwise).
// ---------------------------------------------------------------------------

#define NBATCH 8
#define FBBINS 8192
#define CAP    262144
#define SCAP   2048
#define FINE   1024
#define MCAP   512
#define LO_F   1.26f
#define HI_F   1.31f

__device__ unsigned int g_cnt [NBATCH];
__device__ unsigned int g_hi  [NBATCH];
__device__ unsigned int g_ckey[NBATCH][CAP];
__device__ unsigned int g_cidx[NBATCH][CAP];
__device__ unsigned int g_fhist[NBATCH][FINE];
__device__ unsigned int g_thr [NBATCH];     // f2k key of threshold
__device__ unsigned int g_cut [NBATCH];     // max included idx among ties
__device__ int          g_fail;

// monotonic float -> uint key (larger float => larger key)
__device__ __forceinline__ unsigned int f2k(float f) {
    unsigned int u = __float_as_uint(f);
    return u ^ (0x80000000u | (unsigned int)((int)u >> 31));
}

// ============================ FAST PATH ====================================

struct PAState {
    unsigned int* sh_hist;
    unsigned int* skey;
    unsigned int* sidx;
    unsigned int* s_n;
    unsigned int  b;
};

__device__ __forceinline__ void pa_elem(float x, unsigned int gi, unsigned int LOB,
                                        unsigned int& myhi, const PAState& st) {
    if (x > LO_F) {
        if (x > HI_F) { myhi++; }
        else {
            unsigned int uv = __float_as_uint(x);
            atomicAdd(&st.sh_hist[(uv - LOB) >> 9], 1u);
            unsigned int pos = atomicAdd(st.s_n, 1u);
            if (pos < SCAP) { st.skey[pos] = uv; st.sidx[pos] = gi; }
            else {
                unsigned int gp = atomicAdd(&g_cnt[st.b], 1u);
                if (gp < CAP) { g_ckey[st.b][gp] = uv; g_cidx[st.b][gp] = gi; }
            }
        }
    }
}

__global__ void __launch_bounds__(512) k_passA(const float4* __restrict__ in, int nvec) {
    __shared__ unsigned int sh_hist[FINE];
    __shared__ unsigned int skey[SCAP], sidx[SCAP];
    __shared__ unsigned int s_n, s_base, s_hi;
    const int b = blockIdx.y;
    const unsigned int LOB = __float_as_uint(LO_F);
    for (int i = threadIdx.x; i < FINE; i += blockDim.x) sh_hist[i] = 0;
    if (threadIdx.x == 0) { s_n = 0; s_hi = 0; }
    __syncthreads();
    PAState st { sh_hist, skey, sidx, &s_n, (unsigned int)b };

    const float4* p = in + (size_t)b * nvec;
    const int bd = blockDim.x;
    int per_block = (nvec + gridDim.x - 1) / gridDim.x;
    int start = blockIdx.x * per_block;
    int end   = min(start + per_block, nvec);
    unsigned int myhi = 0;

    int i = start + threadIdx.x;
    // main: 4 independent loads in flight per iteration
    for (; i + 3 * bd < end; i += 4 * bd) {
        float4 v0 = p[i];
        float4 v1 = p[i + bd];
        float4 v2 = p[i + 2 * bd];
        float4 v3 = p[i + 3 * bd];
        unsigned int g0 = (unsigned int)i * 4u;
        unsigned int g1 = (unsigned int)(i + bd) * 4u;
        unsigned int g2 = (unsigned int)(i + 2 * bd) * 4u;
        unsigned int g3 = (unsigned int)(i + 3 * bd) * 4u;
        pa_elem(v0.x, g0 + 0u, LOB, myhi, st); pa_elem(v0.y, g0 + 1u, LOB, myhi, st);
        pa_elem(v0.z, g0 + 2u, LOB, myhi, st); pa_elem(v0.w, g0 + 3u, LOB, myhi, st);
        pa_elem(v1.x, g1 + 0u, LOB, myhi, st); pa_elem(v1.y, g1 + 1u, LOB, myhi, st);
        pa_elem(v1.z, g1 + 2u, LOB, myhi, st); pa_elem(v1.w, g1 + 3u, LOB, myhi, st);
        pa_elem(v2.x, g2 + 0u, LOB, myhi, st); pa_elem(v2.y, g2 + 1u, LOB, myhi, st);
        pa_elem(v2.z, g2 + 2u, LOB, myhi, st); pa_elem(v2.w, g2 + 3u, LOB, myhi, st);
        pa_elem(v3.x, g3 + 0u, LOB, myhi, st); pa_elem(v3.y, g3 + 1u, LOB, myhi, st);
        pa_elem(v3.z, g3 + 2u, LOB, myhi, st); pa_elem(v3.w, g3 + 3u, LOB, myhi, st);
    }
    for (; i < end; i += bd) {
        float4 v = p[i];
        unsigned int g0 = (unsigned int)i * 4u;
        pa_elem(v.x, g0 + 0u, LOB, myhi, st); pa_elem(v.y, g0 + 1u, LOB, myhi, st);
        pa_elem(v.z, g0 + 2u, LOB, myhi, st); pa_elem(v.w, g0 + 3u, LOB, myhi, st);
    }

    #pragma unroll
    for (int o = 16; o > 0; o >>= 1) myhi += __shfl_down_sync(0xFFFFFFFFu, myhi, o);
    if ((threadIdx.x & 31) == 0) atomicAdd(&s_hi, myhi);
    __syncthreads();
    if (threadIdx.x == 0) {
        atomicAdd(&g_hi[b], s_hi);
        unsigned int m = min(s_n, (unsigned int)SCAP);
        s_base = atomicAdd(&g_cnt[b], m);
        s_n = m;
    }
    __syncthreads();
    for (unsigned int j = threadIdx.x; j < s_n; j += blockDim.x) {
        unsigned int gp = s_base + j;
        if (gp < CAP) { g_ckey[b][gp] = skey[j]; g_cidx[b][gp] = sidx[j]; }
    }
    for (int j = threadIdx.x; j < FINE; j += blockDim.x) {
        unsigned int c = sh_hist[j];
        if (c) atomicAdd(&g_fhist[b][j], c);
    }
}

__global__ void k_selectB(int k) {
    __shared__ unsigned int h[FINE];
    __shared__ unsigned int csum[32];
    __shared__ unsigned int s_bsel, s_r;
    __shared__ unsigned int s_key[MCAP];
    __shared__ unsigned int s_m, s_thr, s_extra, s_E;
    __shared__ unsigned int eq_idx[1024];
    __shared__ unsigned int s_neq, s_cut;
    const int b = blockIdx.x;
    const unsigned int n  = g_cnt[b];
    const unsigned int hi = g_hi[b];
    const unsigned int uk = (unsigned int)k;
    bool valid = (n <= CAP) && (hi < uk) && (hi + n >= uk);
    if (!valid) { if (threadIdx.x == 0) g_fail = 1; return; }
    const unsigned int rank = uk - hi;
    for (int i = threadIdx.x; i < FINE; i += blockDim.x) h[i] = g_fhist[b][i];
    if (threadIdx.x == 0) {
        s_m = 0; s_neq = 0; s_cut = 0xFFFFFFFFu;
        s_thr = 0; s_extra = 0; s_E = 0;
    }
    __syncthreads();
    if (threadIdx.x < 32) {
        unsigned int s = 0;
        #pragma unroll
        for (int j = 0; j < 32; j++) s += h[threadIdx.x * 32 + j];
        csum[threadIdx.x] = s;
    }
    __syncthreads();
    if (threadIdx.x == 0) {
        unsigned int cum = 0;
        int c = 31;
        for (; c > 0; c--) {
            if (cum + csum[c] >= rank) break;
            cum += csum[c];
        }
        int bsel = c * 32;
        for (int d = c * 32 + 31; d >= c * 32; d--) {
            if (cum + h[d] >= rank) { bsel = d; break; }
            cum += h[d];
        }
        s_bsel = (unsigned int)bsel;
        s_r    = rank - cum;
    }
    __syncthreads();
    const unsigned int bsel = s_bsel, r = s_r;
    const unsigned int LOB = __float_as_uint(LO_F);
    for (unsigned int i = threadIdx.x; i < n; i += blockDim.x) {
        unsigned int uv = g_ckey[b][i];
        if (((uv - LOB) >> 9) == bsel) {
            unsigned int p = atomicAdd(&s_m, 1u);
            if (p < MCAP) s_key[p] = uv;
        }
    }
    __syncthreads();
    unsigned int m = s_m;
    if (m > MCAP) { if (threadIdx.x == 0) g_fail = 1; return; }
    for (unsigned int j = threadIdx.x; j < m; j += blockDim.x) {
        unsigned int x = s_key[j], cg = 0, ce = 0;
        for (unsigned int t = 0; t < m; t++) {
            unsigned int y = s_key[t];
            cg += (y > x); ce += (y == x);
        }
        if (cg < r && r <= cg + ce) { s_thr = x; s_extra = r - cg; s_E = ce; }
    }
    __syncthreads();
    const unsigned int thr = s_thr, extra = s_extra, E = s_E;
    if (extra < E) {
        for (unsigned int i = threadIdx.x; i < n; i += blockDim.x) {
            if (g_ckey[b][i] == thr) {
                unsigned int p = atomicAdd(&s_neq, 1u);
                if (p < 1024) eq_idx[p] = g_cidx[b][i];
            }
        }
        __syncthreads();
        unsigned int ne = s_neq;
        if (ne > 1024) { if (threadIdx.x == 0) g_fail = 1; return; }
        for (unsigned int j = threadIdx.x; j < ne; j += blockDim.x) {
            unsigned int me = eq_idx[j], c2 = 0;
            for (unsigned int t = 0; t < ne; t++) c2 += (eq_idx[t] <= me);
            if (c2 == extra) s_cut = me;
        }
        __syncthreads();
    }
    if (threadIdx.x == 0) {
        g_thr[b] = thr | 0x80000000u;   // f2k of a positive float
        g_cut[b] = s_cut;
    }
}

// ================== FALLBACK: one kernel, fully general ====================

__global__ void __launch_bounds__(1024) fb_all(const float4* __restrict__ in,
                                               int nvec, int k) {
    if (!g_fail) return;
    __shared__ unsigned int sh[FBBINS];           // hist13 / hist256 / eq_idx
    __shared__ unsigned int s_pref, s_krem, s_n;
    __shared__ unsigned int s_fixedval, s_fixedmask, s_rank, s_E, s_neq, s_cut;
    const int b = blockIdx.x;
    const float4* p = in + (size_t)b * nvec;
    const int bd = blockDim.x;

    for (int i = threadIdx.x; i < FBBINS; i += bd) sh[i] = 0;
    __syncthreads();
    for (int i = threadIdx.x; i < nvec; i += bd) {
        float4 v = p[i];
        atomicAdd(&sh[f2k(v.x) >> 19], 1u);
        atomicAdd(&sh[f2k(v.y) >> 19], 1u);
        atomicAdd(&sh[f2k(v.z) >> 19], 1u);
        atomicAdd(&sh[f2k(v.w) >> 19], 1u);
    }
    __syncthreads();
    if (threadIdx.x == 0) {
        unsigned int cum = 0;
        for (int j = FBBINS - 1; j >= 0; j--) {
            unsigned int c = sh[j];
            if (cum + c >= (unsigned int)k) { s_pref = (unsigned int)j; s_krem = (unsigned int)k - cum; break; }
            cum += c;
        }
        s_n = 0;
    }
    __syncthreads();
    const unsigned int pref = s_pref;
    for (int i = threadIdx.x; i < nvec; i += bd) {
        float4 v = p[i];
        unsigned int kk[4] = { f2k(v.x), f2k(v.y), f2k(v.z), f2k(v.w) };
        #pragma unroll
        for (int j = 0; j < 4; j++) {
            if ((kk[j] >> 19) == pref) {
                unsigned int pos = atomicAdd(&s_n, 1u);
                if (pos < CAP) {
                    g_ckey[b][pos] = kk[j];
                    g_cidx[b][pos] = (unsigned int)i * 4u + (unsigned int)j;
                }
            }
        }
    }
    __syncthreads();
    const unsigned int n = min(s_n, (unsigned int)CAP);
    if (threadIdx.x == 0) {
        s_fixedval = 0; s_fixedmask = 0; s_rank = s_krem; s_E = 0;
        s_neq = 0; s_cut = 0xFFFFFFFFu;
    }
    __syncthreads();
    const int shifts[3] = { 11, 3, 0 };
    const int widths[3] = { 8, 8, 3 };
    for (int r = 0; r < 3; r++) {
        const int s = shifts[r];
        const unsigned int mw = (1u << widths[r]) - 1u;
        for (int i = threadIdx.x; i < 256; i += bd) sh[i] = 0;
        __syncthreads();
        const unsigned int fm = s_fixedmask, fv = s_fixedval;
        for (unsigned int i = threadIdx.x; i < n; i += bd) {
            unsigned int low = g_ckey[b][i] & 0x7FFFFu;
            if ((low & fm) == fv) atomicAdd(&sh[(low >> s) & mw], 1u);
        }
        __syncthreads();
        if (threadIdx.x == 0) {
            unsigned int cum = 0, rank = s_rank, sel = 0;
            for (int d = (int)mw; d >= 0; d--) {
                unsigned int c = sh[d];
                if (cum + c >= rank) { sel = (unsigned int)d; s_rank = rank - cum; s_E = c; break; }
                cum += c;
            }
            s_fixedval  |= sel << s;
            s_fixedmask |= mw  << s;
        }
        __syncthreads();
    }
    const unsigned int thr   = (pref << 19) | s_fixedval;
    const unsigned int extra = s_rank;
    const unsigned int E     = s_E;
    __syncthreads();
    if (extra < E) {
        unsigned int* eq = sh;   // reuse smem (hist no longer needed)
        for (unsigned int i = threadIdx.x; i < n; i += bd) {
            if (g_ckey[b][i] == thr) {
                unsigned int pos = atomicAdd(&s_neq, 1u);
                if (pos < FBBINS) eq[pos] = g_cidx[b][i];
            }
        }
        __syncthreads();
        unsigned int ne = min(s_neq, (unsigned int)FBBINS);
        for (unsigned int j = threadIdx.x; j < ne; j += bd) {
            unsigned int me = eq[j], c = 0;
            for (unsigned int t = 0; t < ne; t++) if (eq[t] <= me) c++;
            if (c == extra) s_cut = me;
        }
        __syncthreads();
    }
    if (threadIdx.x == 0) { g_thr[b] = thr; g_cut[b] = s_cut; }
}

// ============================== WRITE ======================================

__global__ void __launch_bounds__(512) k_write(const float4* __restrict__ in,
                                               float4* __restrict__ out, int nvec) {
    const int b = blockIdx.y;
    const unsigned int thrk = g_thr[b];
    const unsigned int cut  = g_cut[b];
    const float4* p = in  + (size_t)b * nvec;
    float4*       q = out + (size_t)b * nvec;
    const int bd = blockDim.x;
    int per_block = (nvec + gridDim.x - 1) / gridDim.x;
    int start = blockIdx.x * per_block;
    int end   = min(start + per_block, nvec);

    if (thrk > 0x80000000u) {
        // threshold is a positive nonzero float: float-domain compares are
        // exactly order-equivalent to key compares; ties via raw-bit equality.
        const unsigned int tbits = thrk ^ 0x80000000u;
        const float tf = __uint_as_float(tbits);
        int i = start + threadIdx.x;
        for (; i + 3 * bd < end; i += 4 * bd) {
            float4 v0 = p[i];
            float4 v1 = p[i + bd];
            float4 v2 = p[i + 2 * bd];
            float4 v3 = p[i + 3 * bd];
            float4 o0, o1, o2, o3;
            unsigned int g0 = (unsigned int)i * 4u;
            unsigned int g1 = (unsigned int)(i + bd) * 4u;
            unsigned int g2 = (unsigned int)(i + 2 * bd) * 4u;
            unsigned int g3 = (unsigned int)(i + 3 * bd) * 4u;
            #define MSK(x, gi) ((x) > tf || (__float_as_uint(x) == tbits && (gi) <= cut)) ? (x) : 0.0f
            o0.x = MSK(v0.x, g0+0u); o0.y = MSK(v0.y, g0+1u); o0.z = MSK(v0.z, g0+2u); o0.w = MSK(v0.w, g0+3u);
            o1.x = MSK(v1.x, g1+0u); o1.y = MSK(v1.y, g1+1u); o1.z = MSK(v1.z, g1+2u); o1.w = MSK(v1.w, g1+3u);
            o2.x = MSK(v2.x, g2+0u); o2.y = MSK(v2.y, g2+1u); o2.z = MSK(v2.z, g2+2u); o2.w = MSK(v2.w, g2+3u);
            o3.x = MSK(v3.x, g3+0u); o3.y = MSK(v3.y, g3+1u); o3.z = MSK(v3.z, g3+2u); o3.w = MSK(v3.w, g3+3u);
            q[i] = o0; q[i + bd] = o1; q[i + 2 * bd] = o2; q[i + 3 * bd] = o3;
        }
        for (; i < end; i += bd) {
            float4 v = p[i];
            unsigned int g0 = (unsigned int)i * 4u;
            float4 o;
            o.x = MSK(v.x, g0+0u); o.y = MSK(v.y, g0+1u); o.z = MSK(v.z, g0+2u); o.w = MSK(v.w, g0+3u);
            q[i] = o;
            #undef MSK
        }
    } else {
        // general path (fallback thresholds, incl. negatives/zero): key compare
        for (int i = start + threadIdx.x; i < end; i += bd) {
            float4 v = p[i];
            unsigned int base = (unsigned int)i * 4u;
            unsigned int k0 = f2k(v.x), k1 = f2k(v.y), k2 = f2k(v.z), k3 = f2k(v.w);
            float4 o;
            o.x = (k0 > thrk || (k0 == thrk && base + 0u <= cut)) ? v.x : 0.0f;
            o.y = (k1 > thrk || (k1 == thrk && base + 1u <= cut)) ? v.y : 0.0f;
            o.z = (k2 > thrk || (k2 == thrk && base + 2u <= cut)) ? v.z : 0.0f;
            o.w = (k3 > thrk || (k3 == thrk && base + 3u <= cut)) ? v.w : 0.0f;
            q[i] = o;
        }
    }
    // reset scratch for next graph replay
    if (blockIdx.x == 0 && blockIdx.y == 0) {
        for (int i = threadIdx.x; i < NBATCH * FINE; i += bd)
            ((unsigned int*)g_fhist)[i] = 0;
        if (threadIdx.x < NBATCH) { g_cnt[threadIdx.x] = 0; g_hi[threadIdx.x] = 0; }
        if (threadIdx.x == 0) g_fail = 0;
    }
}

// ============================== HOST =======================================

extern "C" void kernel_launch(void* const* d_in, const int* in_sizes, int n_in,
                              void* d_out, int out_size) {
    (void)n_in; (void)out_size;
    const int total = in_sizes[0];           // 33,554,432
    const int N     = total / NBATCH;        // 4,194,304
    int k = (int)((double)N * 0.1);          // 419,430
    if (k < 1) k = 1;
    const int nvec = N / 4;                  // 1,048,576 float4 per row

    const float4* in  = (const float4*)d_in[0];
    float4*       out = (float4*)d_out;

    dim3 gA(256, NBATCH);

    k_passA  <<<gA, 512>>>(in, nvec);
    k_selectB<<<NBATCH, 256>>>(k);
    fb_all   <<<NBATCH, 1024>>>(in, nvec, k);
    k_write  <<<gA, 512>>>(in, out, nvec);
}

// round 5
// speedup vs baseline: 1.2435x; 1.2435x over previous
#include <cuda_runtime.h>
#include <stdint.h>

// ---------------------------------------------------------------------------
// LateralInhibition: per-batch top-k masking (B=8, N=4,194,304, k=419,430).
//
// 3 launches:
//   passA : read 128MB, MLP-4, branch-lean. counts v>HI; warp-aggregated
//           staging of window candidates (LO<v<=HI). Last block per row
//           (arrive-counter) runs the exact select on L2-hot candidates:
//           1024-bin hist -> boundary bin -> exact threshold + tie cutoff.
//   fb_all: gated on g_fail; fully-general exact select (8 blocks). ~1us
//           early-exit on the fast path.
//   write : masked write, reverse traversal (L2 reuse of passA's tail) +
//           __stcs streaming stores + scratch reset for next replay.
// ---------------------------------------------------------------------------

#define NBATCH 8
#define FBBINS 8192
#define CAP    262144
#define SCAP   2048
#define FINE   1024
#define MCAP   512
#define LO_F   1.26f
#define HI_F   1.31f

__device__ unsigned int g_cnt [NBATCH];
__device__ unsigned int g_hi  [NBATCH];
__device__ unsigned int g_arrive[NBATCH];
__device__ unsigned int g_ckey[NBATCH][CAP];
__device__ unsigned int g_cidx[NBATCH][CAP];
__device__ unsigned int g_thr [NBATCH];     // f2k key of threshold
__device__ unsigned int g_cut [NBATCH];     // max included idx among ties
__device__ int          g_fail;

// monotonic float -> uint key (larger float => larger key)
__device__ __forceinline__ unsigned int f2k(float f) {
    unsigned int u = __float_as_uint(f);
    return u ^ (0x80000000u | (unsigned int)((int)u >> 31));
}

// ============================ PASS A + SELECT ==============================

__global__ void __launch_bounds__(512) k_passA(const float4* __restrict__ in,
                                               int nvec, int k) {
    __shared__ unsigned int skey[SCAP], sidx[SCAP];   // staging; reused by select
    __shared__ unsigned int s_n, s_base, s_hi, s_last;
    __shared__ unsigned int s_bsel, s_r, s_m, s_thr, s_extra, s_E, s_neq, s_cut;
    __shared__ unsigned int csum[32];
    const int b   = blockIdx.y;
    const int bd  = blockDim.x;
    const int tid = threadIdx.x;
    const int lane = tid & 31;
    if (tid == 0) { s_n = 0; s_hi = 0; }
    __syncthreads();

    const float4* p = in + (size_t)b * nvec;
    int per_block = (nvec + gridDim.x - 1) / gridDim.x;
    int start = blockIdx.x * per_block;
    int end   = min(start + per_block, nvec);
    unsigned int myhi = 0;

    // warp-aggregated candidate push (converged call sites only)
    #define PA_ELEM(x, gi) do {                                              \
        float _x = (x);                                                      \
        myhi += (_x > HI_F) ? 1u : 0u;                                       \
        bool _w = (_x > LO_F) && (_x <= HI_F);                               \
        unsigned int _m = __ballot_sync(0xFFFFFFFFu, _w);                    \
        if (_m) {                                                            \
            int _ldr = __ffs(_m) - 1;                                        \
            unsigned int _pb = 0;                                            \
            if (lane == _ldr) _pb = atomicAdd(&s_n, (unsigned)__popc(_m));   \
            _pb = __shfl_sync(0xFFFFFFFFu, _pb, _ldr);                       \
            if (_w) {                                                        \
                unsigned int _p = _pb + __popc(_m & ((1u << lane) - 1u));    \
                if (_p < SCAP) { skey[_p] = __float_as_uint(_x); sidx[_p] = (gi); } \
            }                                                                \
        }                                                                    \
    } while (0)

    int i = start + tid;
    for (; i + 3 * bd < end; i += 4 * bd) {
        float4 v0 = p[i];
        float4 v1 = p[i + bd];
        float4 v2 = p[i + 2 * bd];
        float4 v3 = p[i + 3 * bd];
        unsigned int g0 = (unsigned int)i * 4u;
        unsigned int g1 = (unsigned int)(i + bd) * 4u;
        unsigned int g2 = (unsigned int)(i + 2 * bd) * 4u;
        unsigned int g3 = (unsigned int)(i + 3 * bd) * 4u;
        PA_ELEM(v0.x, g0 + 0u); PA_ELEM(v0.y, g0 + 1u);
        PA_ELEM(v0.z, g0 + 2u); PA_ELEM(v0.w, g0 + 3u);
        PA_ELEM(v1.x, g1 + 0u); PA_ELEM(v1.y, g1 + 1u);
        PA_ELEM(v1.z, g1 + 2u); PA_ELEM(v1.w, g1 + 3u);
        PA_ELEM(v2.x, g2 + 0u); PA_ELEM(v2.y, g2 + 1u);
        PA_ELEM(v2.z, g2 + 2u); PA_ELEM(v2.w, g2 + 3u);
        PA_ELEM(v3.x, g3 + 0u); PA_ELEM(v3.y, g3 + 1u);
        PA_ELEM(v3.z, g3 + 2u); PA_ELEM(v3.w, g3 + 3u);
    }
    #undef PA_ELEM
    // remainder (not taken for the bench shape): per-lane push, no ballot
    for (; i < end; i += bd) {
        float4 v = p[i];
        unsigned int g0 = (unsigned int)i * 4u;
        float xs[4] = { v.x, v.y, v.z, v.w };
        #pragma unroll
        for (int j = 0; j < 4; j++) {
            float x = xs[j];
            myhi += (x > HI_F) ? 1u : 0u;
            if (x > LO_F && x <= HI_F) {
                unsigned int pos = atomicAdd(&s_n, 1u);
                if (pos < SCAP) { skey[pos] = __float_as_uint(x); sidx[pos] = g0 + (unsigned)j; }
            }
        }
    }

    #pragma unroll
    for (int o = 16; o > 0; o >>= 1) myhi += __shfl_down_sync(0xFFFFFFFFu, myhi, o);
    if (lane == 0) atomicAdd(&s_hi, myhi);
    __syncthreads();
    if (tid == 0) {
        if (s_n > SCAP) g_fail = 1;          // staging overflow -> fallback
        unsigned int m = min(s_n, (unsigned int)SCAP);
        atomicAdd(&g_hi[b], s_hi);
        s_base = atomicAdd(&g_cnt[b], m);
        s_n = m;
    }
    __syncthreads();
    for (unsigned int j = tid; j < s_n; j += bd) {
        unsigned int gp = s_base + j;
        if (gp < CAP) { g_ckey[b][gp] = skey[j]; g_cidx[b][gp] = sidx[j]; }
    }
    __syncthreads();
    __threadfence();
    if (tid == 0)
        s_last = (atomicAdd(&g_arrive[b], 1u) == gridDim.x - 1u) ? 1u : 0u;
    __syncthreads();
    if (!s_last) return;

    // ================= last block of this row: exact select ================
    __threadfence();
    const unsigned int n  = g_cnt[b];
    const unsigned int hi = g_hi[b];
    const unsigned int uk = (unsigned int)k;
    if (!((n <= CAP) && (hi < uk) && (hi + n >= uk))) {
        if (tid == 0) g_fail = 1;
        return;
    }
    const unsigned int rank = uk - hi;
    const unsigned int LOB = __float_as_uint(LO_F);
    unsigned int* h  = skey;     // reuse staging smem: h[FINE]
    unsigned int* aux = sidx;    // reuse: boundary keys / eq indices

    for (int j = tid; j < FINE; j += bd) h[j] = 0;
    if (tid == 0) { s_m = 0; s_neq = 0; s_cut = 0xFFFFFFFFu; s_thr = 0; s_extra = 0; s_E = 0; }
    __syncthreads();
    for (unsigned int j = tid; j < n; j += bd)
        atomicAdd(&h[(g_ckey[b][j] - LOB) >> 9], 1u);
    __syncthreads();
    if (tid < 32) {
        unsigned int s = 0;
        #pragma unroll
        for (int t = 0; t < 32; t++) s += h[tid * 32 + t];
        csum[tid] = s;
    }
    __syncthreads();
    if (tid == 0) {
        unsigned int cum = 0;
        int c = 31;
        for (; c > 0; c--) {
            if (cum + csum[c] >= rank) break;
            cum += csum[c];
        }
        int bsel = c * 32;
        for (int d = c * 32 + 31; d >= c * 32; d--) {
            if (cum + h[d] >= rank) { bsel = d; break; }
            cum += h[d];
        }
        s_bsel = (unsigned int)bsel;
        s_r    = rank - cum;
    }
    __syncthreads();
    const unsigned int bsel = s_bsel, r = s_r;
    for (unsigned int j = tid; j < n; j += bd) {
        unsigned int uv = g_ckey[b][j];
        if (((uv - LOB) >> 9) == bsel) {
            unsigned int pp = atomicAdd(&s_m, 1u);
            if (pp < MCAP) aux[pp] = uv;
        }
    }
    __syncthreads();
    unsigned int m = s_m;
    if (m > MCAP) { if (tid == 0) g_fail = 1; return; }
    for (unsigned int j = tid; j < m; j += bd) {
        unsigned int x = aux[j], cg = 0, ce = 0;
        for (unsigned int t = 0; t < m; t++) {
            unsigned int y = aux[t];
            cg += (y > x); ce += (y == x);
        }
        if (cg < r && r <= cg + ce) { s_thr = x; s_extra = r - cg; s_E = ce; }
    }
    __syncthreads();
    const unsigned int thr = s_thr, extra = s_extra, E = s_E;
    if (extra < E) {   // tie-break: extra-th smallest index among equals
        for (unsigned int j = tid; j < n; j += bd) {
            if (g_ckey[b][j] == thr) {
                unsigned int pp = atomicAdd(&s_neq, 1u);
                if (pp < SCAP) aux[pp] = g_cidx[b][j];
            }
        }
        __syncthreads();
        unsigned int ne = s_neq;
        if (ne > SCAP) { if (tid == 0) g_fail = 1; return; }
        for (unsigned int j = tid; j < ne; j += bd) {
            unsigned int me = aux[j], c2 = 0;
            for (unsigned int t = 0; t < ne; t++) c2 += (aux[t] <= me);
            if (c2 == extra) s_cut = me;
        }
        __syncthreads();
    }
    if (tid == 0) {
        g_thr[b] = thr | 0x80000000u;   // f2k of a positive float
        g_cut[b] = s_cut;
    }
}

// ================== FALLBACK: one kernel, fully general ====================

__global__ void __launch_bounds__(1024) fb_all(const float4* __restrict__ in,
                                               int nvec, int k) {
    if (!g_fail) return;
    __shared__ unsigned int sh[FBBINS];
    __shared__ unsigned int s_pref, s_krem, s_n;
    __shared__ unsigned int s_fixedval, s_fixedmask, s_rank, s_E, s_neq, s_cut;
    const int b = blockIdx.x;
    const float4* p = in + (size_t)b * nvec;
    const int bd = blockDim.x;

    for (int i = threadIdx.x; i < FBBINS; i += bd) sh[i] = 0;
    __syncthreads();
    for (int i = threadIdx.x; i < nvec; i += bd) {
        float4 v = p[i];
        atomicAdd(&sh[f2k(v.x) >> 19], 1u);
        atomicAdd(&sh[f2k(v.y) >> 19], 1u);
        atomicAdd(&sh[f2k(v.z) >> 19], 1u);
        atomicAdd(&sh[f2k(v.w) >> 19], 1u);
    }
    __syncthreads();
    if (threadIdx.x == 0) {
        unsigned int cum = 0;
        for (int j = FBBINS - 1; j >= 0; j--) {
            unsigned int c = sh[j];
            if (cum + c >= (unsigned int)k) { s_pref = (unsigned int)j; s_krem = (unsigned int)k - cum; break; }
            cum += c;
        }
        s_n = 0;
    }
    __syncthreads();
    const unsigned int pref = s_pref;
    for (int i = threadIdx.x; i < nvec; i += bd) {
        float4 v = p[i];
        unsigned int kk[4] = { f2k(v.x), f2k(v.y), f2k(v.z), f2k(v.w) };
        #pragma unroll
        for (int j = 0; j < 4; j++) {
            if ((kk[j] >> 19) == pref) {
                unsigned int pos = atomicAdd(&s_n, 1u);
                if (pos < CAP) {
                    g_ckey[b][pos] = kk[j];
                    g_cidx[b][pos] = (unsigned int)i * 4u + (unsigned int)j;
                }
            }
        }
    }
    __syncthreads();
    const unsigned int n = min(s_n, (unsigned int)CAP);
    if (threadIdx.x == 0) {
        s_fixedval = 0; s_fixedmask = 0; s_rank = s_krem; s_E = 0;
        s_neq = 0; s_cut = 0xFFFFFFFFu;
    }
    __syncthreads();
    const int shifts[3] = { 11, 3, 0 };
    const int widths[3] = { 8, 8, 3 };
    for (int r = 0; r < 3; r++) {
        const int s = shifts[r];
        const unsigned int mw = (1u << widths[r]) - 1u;
        for (int i = threadIdx.x; i < 256; i += bd) sh[i] = 0;
        __syncthreads();
        const unsigned int fm = s_fixedmask, fv = s_fixedval;
        for (unsigned int i = threadIdx.x; i < n; i += bd) {
            unsigned int low = g_ckey[b][i] & 0x7FFFFu;
            if ((low & fm) == fv) atomicAdd(&sh[(low >> s) & mw], 1u);
        }
        __syncthreads();
        if (threadIdx.x == 0) {
            unsigned int cum = 0, rank = s_rank, sel = 0;
            for (int d = (int)mw; d >= 0; d--) {
                unsigned int c = sh[d];
                if (cum + c >= rank) { sel = (unsigned int)d; s_rank = rank - cum; s_E = c; break; }
                cum += c;
            }
            s_fixedval  |= sel << s;
            s_fixedmask |= mw  << s;
        }
        __syncthreads();
    }
    const unsigned int thr   = (pref << 19) | s_fixedval;
    const unsigned int extra = s_rank;
    const unsigned int E     = s_E;
    __syncthreads();
    if (extra < E) {
        unsigned int* eq = sh;
        for (unsigned int i = threadIdx.x; i < n; i += bd) {
            if (g_ckey[b][i] == thr) {
                unsigned int pos = atomicAdd(&s_neq, 1u);
                if (pos < FBBINS) eq[pos] = g_cidx[b][i];
            }
        }
        __syncthreads();
        unsigned int ne = min(s_neq, (unsigned int)FBBINS);
        for (unsigned int j = threadIdx.x; j < ne; j += bd) {
            unsigned int me = eq[j], c = 0;
            for (unsigned int t = 0; t < ne; t++) if (eq[t] <= me) c++;
            if (c == extra) s_cut = me;
        }
        __syncthreads();
    }
    if (threadIdx.x == 0) { g_thr[b] = thr; g_cut[b] = s_cut; }
}

// ============================== WRITE ======================================

__global__ void __launch_bounds__(512) k_write(const float4* __restrict__ in,
                                               float4* __restrict__ out, int nvec) {
    const int b = blockIdx.y;
    const unsigned int thrk = g_thr[b];
    const unsigned int cut  = g_cut[b];
    const float4* p = in  + (size_t)b * nvec;
    float4*       q = out + (size_t)b * nvec;
    const int bd = blockDim.x;
    // reverse chunk order: start where passA's L2 footprint is freshest
    const int chunk = gridDim.x - 1 - blockIdx.x;
    int per_block = (nvec + gridDim.x - 1) / gridDim.x;
    int start = chunk * per_block;
    int end   = min(start + per_block, nvec);

    if (thrk > 0x80000000u) {
        const unsigned int tbits = thrk ^ 0x80000000u;
        const float tf = __uint_as_float(tbits);
        int i = start + threadIdx.x;
        for (; i + 3 * bd < end; i += 4 * bd) {
            float4 v0 = p[i];
            float4 v1 = p[i + bd];
            float4 v2 = p[i + 2 * bd];
            float4 v3 = p[i + 3 * bd];
            float4 o0, o1, o2, o3;
            unsigned int g0 = (unsigned int)i * 4u;
            unsigned int g1 = (unsigned int)(i + bd) * 4u;
            unsigned int g2 = (unsigned int)(i + 2 * bd) * 4u;
            unsigned int g3 = (unsigned int)(i + 3 * bd) * 4u;
            #define MSK(x, gi) ((x) > tf || (__float_as_uint(x) == tbits && (gi) <= cut)) ? (x) : 0.0f
            o0.x = MSK(v0.x, g0+0u); o0.y = MSK(v0.y, g0+1u); o0.z = MSK(v0.z, g0+2u); o0.w = MSK(v0.w, g0+3u);
            o1.x = MSK(v1.x, g1+0u); o1.y = MSK(v1.y, g1+1u); o1.z = MSK(v1.z, g1+2u); o1.w = MSK(v1.w, g1+3u);
            o2.x = MSK(v2.x, g2+0u); o2.y = MSK(v2.y, g2+1u); o2.z = MSK(v2.z, g2+2u); o2.w = MSK(v2.w, g2+3u);
            o3.x = MSK(v3.x, g3+0u); o3.y = MSK(v3.y, g3+1u); o3.z = MSK(v3.z, g3+2u); o3.w = MSK(v3.w, g3+3u);
            __stcs(&q[i], o0);
            __stcs(&q[i + bd], o1);
            __stcs(&q[i + 2 * bd], o2);
            __stcs(&q[i + 3 * bd], o3);
        }
        for (; i < end; i += bd) {
            float4 v = p[i];
            unsigned int g0 = (unsigned int)i * 4u;
            float4 o;
            o.x = MSK(v.x, g0+0u); o.y = MSK(v.y, g0+1u); o.z = MSK(v.z, g0+2u); o.w = MSK(v.w, g0+3u);
            __stcs(&q[i], o);
            #undef MSK
        }
    } else {
        for (int i = start + threadIdx.x; i < end; i += bd) {
            float4 v = p[i];
            unsigned int base = (unsigned int)i * 4u;
            unsigned int k0 = f2k(v.x), k1 = f2k(v.y), k2 = f2k(v.z), k3 = f2k(v.w);
            float4 o;
            o.x = (k0 > thrk || (k0 == thrk && base + 0u <= cut)) ? v.x : 0.0f;
            o.y = (k1 > thrk || (k1 == thrk && base + 1u <= cut)) ? v.y : 0.0f;
            o.z = (k2 > thrk || (k2 == thrk && base + 2u <= cut)) ? v.z : 0.0f;
            o.w = (k3 > thrk || (k3 == thrk && base + 3u <= cut)) ? v.w : 0.0f;
            __stcs(&q[i], o);
        }
    }
    // reset scratch for next graph replay
    if (blockIdx.x == 0 && blockIdx.y == 0) {
        if (threadIdx.x < NBATCH) {
            g_cnt[threadIdx.x] = 0;
            g_hi[threadIdx.x] = 0;
            g_arrive[threadIdx.x] = 0;
        }
        if (threadIdx.x == 0) g_fail = 0;
    }
}

// ============================== HOST =======================================

extern "C" void kernel_launch(void* const* d_in, const int* in_sizes, int n_in,
                              void* d_out, int out_size) {
    (void)n_in; (void)out_size;
    const int total = in_sizes[0];           // 33,554,432
    const int N     = total / NBATCH;        // 4,194,304
    int k = (int)((double)N * 0.1);          // 419,430
    if (k < 1) k = 1;
    const int nvec = N / 4;                  // 1,048,576 float4 per row

    const float4* in  = (const float4*)d_in[0];
    float4*       out = (float4*)d_out;

    dim3 gA(256, NBATCH);

    k_passA<<<gA, 512>>>(in, nvec, k);
    fb_all <<<NBATCH, 1024>>>(in, nvec, k);
    k_write<<<gA, 512>>>(in, out, nvec);
}

// round 6
// speedup vs baseline: 1.3143x; 1.0569x over previous
#include <cuda_runtime.h>
#include <stdint.h>

// ---------------------------------------------------------------------------
// LateralInhibition: per-batch top-k masking (B=8, N=4,194,304, k=419,430).
//
// 3 launches:
//   passA : read 128MB, MLP-4, lean hot loop (1 float cmp + 1 uint cmp per
//           element). counts x>LO; stages window candidates (LO<x<=HI).
//           Last block per row (arrive-counter) runs exact select on the
//           L2-hot candidate list: 1024-bin hist -> threshold + tie cutoff.
//   fb_all: gated on g_fail; fully-general exact select. ~1us early-exit.
//   write : masked write, reverse traversal + __stcs streaming stores +
//           scratch reset for next replay.
// ---------------------------------------------------------------------------

#define NBATCH 8
#define FBBINS 8192
#define CAP    262144
#define SCAP   2048
#define FINE   1024
#define MCAP   512
#define LO_F   1.26f
#define HI_F   1.31f

__device__ unsigned int g_cnt [NBATCH];     // window candidates per row
__device__ unsigned int g_gt  [NBATCH];     // count of x > LO per row
__device__ unsigned int g_arrive[NBATCH];
__device__ unsigned int g_ckey[NBATCH][CAP];
__device__ unsigned int g_cidx[NBATCH][CAP];
__device__ unsigned int g_thr [NBATCH];     // f2k key of threshold
__device__ unsigned int g_cut [NBATCH];     // max included idx among ties
__device__ int          g_fail;

// monotonic float -> uint key (larger float => larger key)
__device__ __forceinline__ unsigned int f2k(float f) {
    unsigned int u = __float_as_uint(f);
    return u ^ (0x80000000u | (unsigned int)((int)u >> 31));
}

// ============================ PASS A + SELECT ==============================

__global__ void __launch_bounds__(512) k_passA(const float4* __restrict__ in,
                                               int nvec, int k) {
    __shared__ unsigned int skey[SCAP], sidx[SCAP];   // staging; reused by select
    __shared__ unsigned int s_n, s_base, s_gt, s_last;
    __shared__ unsigned int s_bsel, s_r, s_m, s_thr, s_extra, s_E, s_neq, s_cut;
    __shared__ unsigned int csum[32];
    const int b   = blockIdx.y;
    const int bd  = blockDim.x;
    const int tid = threadIdx.x;
    if (tid == 0) { s_n = 0; s_gt = 0; }
    __syncthreads();

    const float4* p = in + (size_t)b * nvec;
    int per_block = (nvec + gridDim.x - 1) / gridDim.x;
    int start = blockIdx.x * per_block;
    int end   = min(start + per_block, nvec);
    unsigned int mygt = 0;

    const unsigned int LOB = __float_as_uint(LO_F);
    const unsigned int WID = __float_as_uint(HI_F) - LOB;   // window width (bits)

    // Per element: mygt += (x > LO); window iff bits(x)-LOB <= WID
    // (wraps to huge for x<=LO, x<0, NaN/Inf -> single unsigned compare).
    #define PA_ELEM(x, gi) do {                                              \
        float _x = (x);                                                      \
        mygt += (_x > LO_F) ? 1u : 0u;                                       \
        if (__float_as_uint(_x) - LOB <= WID) {                              \
            unsigned int _p = atomicAdd(&s_n, 1u);                           \
            if (_p < SCAP) { skey[_p] = __float_as_uint(_x); sidx[_p] = (gi); } \
        }                                                                    \
    } while (0)

    int i = start + tid;
    for (; i + 3 * bd < end; i += 4 * bd) {
        float4 v0 = p[i];
        float4 v1 = p[i + bd];
        float4 v2 = p[i + 2 * bd];
        float4 v3 = p[i + 3 * bd];
        unsigned int g0 = (unsigned int)i * 4u;
        unsigned int g1 = (unsigned int)(i + bd) * 4u;
        unsigned int g2 = (unsigned int)(i + 2 * bd) * 4u;
        unsigned int g3 = (unsigned int)(i + 3 * bd) * 4u;
        PA_ELEM(v0.x, g0 + 0u); PA_ELEM(v0.y, g0 + 1u);
        PA_ELEM(v0.z, g0 + 2u); PA_ELEM(v0.w, g0 + 3u);
        PA_ELEM(v1.x, g1 + 0u); PA_ELEM(v1.y, g1 + 1u);
        PA_ELEM(v1.z, g1 + 2u); PA_ELEM(v1.w, g1 + 3u);
        PA_ELEM(v2.x, g2 + 0u); PA_ELEM(v2.y, g2 + 1u);
        PA_ELEM(v2.z, g2 + 2u); PA_ELEM(v2.w, g2 + 3u);
        PA_ELEM(v3.x, g3 + 0u); PA_ELEM(v3.y, g3 + 1u);
        PA_ELEM(v3.z, g3 + 2u); PA_ELEM(v3.w, g3 + 3u);
    }
    for (; i < end; i += bd) {
        float4 v = p[i];
        unsigned int g0 = (unsigned int)i * 4u;
        PA_ELEM(v.x, g0 + 0u); PA_ELEM(v.y, g0 + 1u);
        PA_ELEM(v.z, g0 + 2u); PA_ELEM(v.w, g0 + 3u);
    }
    #undef PA_ELEM

    #pragma unroll
    for (int o = 16; o > 0; o >>= 1) mygt += __shfl_down_sync(0xFFFFFFFFu, mygt, o);
    if ((tid & 31) == 0) atomicAdd(&s_gt, mygt);
    __syncthreads();
    if (tid == 0) {
        if (s_n > SCAP) g_fail = 1;          // staging overflow -> fallback
        unsigned int m = min(s_n, (unsigned int)SCAP);
        atomicAdd(&g_gt[b], s_gt);
        s_base = atomicAdd(&g_cnt[b], m);
        s_n = m;
    }
    __syncthreads();
    for (unsigned int j = tid; j < s_n; j += bd) {
        unsigned int gp = s_base + j;
        if (gp < CAP) { g_ckey[b][gp] = skey[j]; g_cidx[b][gp] = sidx[j]; }
    }
    __syncthreads();
    __threadfence();
    if (tid == 0)
        s_last = (atomicAdd(&g_arrive[b], 1u) == gridDim.x - 1u) ? 1u : 0u;
    __syncthreads();
    if (!s_last) return;

    // ================= last block of this row: exact select ================
    __threadfence();
    const unsigned int n  = g_cnt[b];
    const unsigned int gt = g_gt[b];
    const unsigned int uk = (unsigned int)k;
    // hi = gt - n (count strictly above window). valid window position:
    //   hi < k          <=> gt - n < k
    //   hi + n >= k     <=> gt >= k
    if (!((n <= CAP) && (n <= gt) && (gt - n < uk) && (gt >= uk))) {
        if (tid == 0) g_fail = 1;
        return;
    }
    const unsigned int rank = uk - (gt - n);   // 1-based rank within window
    const unsigned int LOB2 = __float_as_uint(LO_F);
    unsigned int* h   = skey;    // reuse staging smem: h[FINE]
    unsigned int* aux = sidx;    // reuse: boundary keys / eq indices

    for (int j = tid; j < FINE; j += bd) h[j] = 0;
    if (tid == 0) { s_m = 0; s_neq = 0; s_cut = 0xFFFFFFFFu; s_thr = 0; s_extra = 0; s_E = 0; }
    __syncthreads();
    for (unsigned int j = tid; j < n; j += bd)
        atomicAdd(&h[(g_ckey[b][j] - LOB2) >> 9], 1u);
    __syncthreads();
    if (tid < 32) {
        unsigned int s = 0;
        #pragma unroll
        for (int t = 0; t < 32; t++) s += h[tid * 32 + t];
        csum[tid] = s;
    }
    __syncthreads();
    if (tid == 0) {
        unsigned int cum = 0;
        int c = 31;
        for (; c > 0; c--) {
            if (cum + csum[c] >= rank) break;
            cum += csum[c];
        }
        int bsel = c * 32;
        for (int d = c * 32 + 31; d >= c * 32; d--) {
            if (cum + h[d] >= rank) { bsel = d; break; }
            cum += h[d];
        }
        s_bsel = (unsigned int)bsel;
        s_r    = rank - cum;
    }
    __syncthreads();
    const unsigned int bsel = s_bsel, r = s_r;
    for (unsigned int j = tid; j < n; j += bd) {
        unsigned int uv = g_ckey[b][j];
        if (((uv - LOB2) >> 9) == bsel) {
            unsigned int pp = atomicAdd(&s_m, 1u);
            if (pp < MCAP) aux[pp] = uv;
        }
    }
    __syncthreads();
    unsigned int m = s_m;
    if (m > MCAP) { if (tid == 0) g_fail = 1; return; }
    for (unsigned int j = tid; j < m; j += bd) {
        unsigned int x = aux[j], cg = 0, ce = 0;
        for (unsigned int t = 0; t < m; t++) {
            unsigned int y = aux[t];
            cg += (y > x); ce += (y == x);
        }
        if (cg < r && r <= cg + ce) { s_thr = x; s_extra = r - cg; s_E = ce; }
    }
    __syncthreads();
    const unsigned int thr = s_thr, extra = s_extra, E = s_E;
    if (extra < E) {   // tie-break: extra-th smallest index among equals
        for (unsigned int j = tid; j < n; j += bd) {
            if (g_ckey[b][j] == thr) {
                unsigned int pp = atomicAdd(&s_neq, 1u);
                if (pp < SCAP) aux[pp] = g_cidx[b][j];
            }
        }
        __syncthreads();
        unsigned int ne = s_neq;
        if (ne > SCAP) { if (tid == 0) g_fail = 1; return; }
        for (unsigned int j = tid; j < ne; j += bd) {
            unsigned int me = aux[j], c2 = 0;
            for (unsigned int t = 0; t < ne; t++) c2 += (aux[t] <= me);
            if (c2 == extra) s_cut = me;
        }
        __syncthreads();
    }
    if (tid == 0) {
        g_thr[b] = thr | 0x80000000u;   // f2k of a positive float
        g_cut[b] = s_cut;
    }
}

// ================== FALLBACK: one kernel, fully general ====================

__global__ void __launch_bounds__(1024) fb_all(const float4* __restrict__ in,
                                               int nvec, int k) {
    if (!g_fail) return;
    __shared__ unsigned int sh[FBBINS];
    __shared__ unsigned int s_pref, s_krem, s_n;
    __shared__ unsigned int s_fixedval, s_fixedmask, s_rank, s_E, s_neq, s_cut;
    const int b = blockIdx.x;
    const float4* p = in + (size_t)b * nvec;
    const int bd = blockDim.x;

    for (int i = threadIdx.x; i < FBBINS; i += bd) sh[i] = 0;
    __syncthreads();
    for (int i = threadIdx.x; i < nvec; i += bd) {
        float4 v = p[i];
        atomicAdd(&sh[f2k(v.x) >> 19], 1u);
        atomicAdd(&sh[f2k(v.y) >> 19], 1u);
        atomicAdd(&sh[f2k(v.z) >> 19], 1u);
        atomicAdd(&sh[f2k(v.w) >> 19], 1u);
    }
    __syncthreads();
    if (threadIdx.x == 0) {
        unsigned int cum = 0;
        for (int j = FBBINS - 1; j >= 0; j--) {
            unsigned int c = sh[j];
            if (cum + c >= (unsigned int)k) { s_pref = (unsigned int)j; s_krem = (unsigned int)k - cum; break; }
            cum += c;
        }
        s_n = 0;
    }
    __syncthreads();
    const unsigned int pref = s_pref;
    for (int i = threadIdx.x; i < nvec; i += bd) {
        float4 v = p[i];
        unsigned int kk[4] = { f2k(v.x), f2k(v.y), f2k(v.z), f2k(v.w) };
        #pragma unroll
        for (int j = 0; j < 4; j++) {
            if ((kk[j] >> 19) == pref) {
                unsigned int pos = atomicAdd(&s_n, 1u);
                if (pos < CAP) {
                    g_ckey[b][pos] = kk[j];
                    g_cidx[b][pos] = (unsigned int)i * 4u + (unsigned int)j;
                }
            }
        }
    }
    __syncthreads();
    const unsigned int n = min(s_n, (unsigned int)CAP);
    if (threadIdx.x == 0) {
        s_fixedval = 0; s_fixedmask = 0; s_rank = s_krem; s_E = 0;
        s_neq = 0; s_cut = 0xFFFFFFFFu;
    }
    __syncthreads();
    const int shifts[3] = { 11, 3, 0 };
    const int widths[3] = { 8, 8, 3 };
    for (int r = 0; r < 3; r++) {
        const int s = shifts[r];
        const unsigned int mw = (1u << widths[r]) - 1u;
        for (int i = threadIdx.x; i < 256; i += bd) sh[i] = 0;
        __syncthreads();
        const unsigned int fm = s_fixedmask, fv = s_fixedval;
        for (unsigned int i = threadIdx.x; i < n; i += bd) {
            unsigned int low = g_ckey[b][i] & 0x7FFFFu;
            if ((low & fm) == fv) atomicAdd(&sh[(low >> s) & mw], 1u);
        }
        __syncthreads();
        if (threadIdx.x == 0) {
            unsigned int cum = 0, rank = s_rank, sel = 0;
            for (int d = (int)mw; d >= 0; d--) {
                unsigned int c = sh[d];
                if (cum + c >= rank) { sel = (unsigned int)d; s_rank = rank - cum; s_E = c; break; }
                cum += c;
            }
            s_fixedval  |= sel << s;
            s_fixedmask |= mw  << s;
        }
        __syncthreads();
    }
    const unsigned int thr   = (pref << 19) | s_fixedval;
    const unsigned int extra = s_rank;
    const unsigned int E     = s_E;
    __syncthreads();
    if (extra < E) {
        unsigned int* eq = sh;
        for (unsigned int i = threadIdx.x; i < n; i += bd) {
            if (g_ckey[b][i] == thr) {
                unsigned int pos = atomicAdd(&s_neq, 1u);
                if (pos < FBBINS) eq[pos] = g_cidx[b][i];
            }
        }
        __syncthreads();
        unsigned int ne = min(s_neq, (unsigned int)FBBINS);
        for (unsigned int j = threadIdx.x; j < ne; j += bd) {
            unsigned int me = eq[j], c = 0;
            for (unsigned int t = 0; t < ne; t++) if (eq[t] <= me) c++;
            if (c == extra) s_cut = me;
        }
        __syncthreads();
    }
    if (threadIdx.x == 0) { g_thr[b] = thr; g_cut[b] = s_cut; }
}

// ============================== WRITE ======================================

__global__ void __launch_bounds__(512) k_write(const float4* __restrict__ in,
                                               float4* __restrict__ out, int nvec) {
    const int b = blockIdx.y;
    const unsigned int thrk = g_thr[b];
    const unsigned int cut  = g_cut[b];
    const float4* p = in  + (size_t)b * nvec;
    float4*       q = out + (size_t)b * nvec;
    const int bd = blockDim.x;
    // reverse chunk order: start where passA's L2 footprint is freshest
    const int chunk = gridDim.x - 1 - blockIdx.x;
    int per_block = (nvec + gridDim.x - 1) / gridDim.x;
    int start = chunk * per_block;
    int end   = min(start + per_block, nvec);

    if (thrk > 0x80000000u) {
        const unsigned int tbits = thrk ^ 0x80000000u;
        const float tf = __uint_as_float(tbits);
        int i = start + threadIdx.x;
        for (; i + 3 * bd < end; i += 4 * bd) {
            float4 v0 = p[i];
            float4 v1 = p[i + bd];
            float4 v2 = p[i + 2 * bd];
            float4 v3 = p[i + 3 * bd];
            float4 o0, o1, o2, o3;
            unsigned int g0 = (unsigned int)i * 4u;
            unsigned int g1 = (unsigned int)(i + bd) * 4u;
            unsigned int g2 = (unsigned int)(i + 2 * bd) * 4u;
            unsigned int g3 = (unsigned int)(i + 3 * bd) * 4u;
            #define MSK(x, gi) ((x) > tf || (__float_as_uint(x) == tbits && (gi) <= cut)) ? (x) : 0.0f
            o0.x = MSK(v0.x, g0+0u); o0.y = MSK(v0.y, g0+1u); o0.z = MSK(v0.z, g0+2u); o0.w = MSK(v0.w, g0+3u);
            o1.x = MSK(v1.x, g1+0u); o1.y = MSK(v1.y, g1+1u); o1.z = MSK(v1.z, g1+2u); o1.w = MSK(v1.w, g1+3u);
            o2.x = MSK(v2.x, g2+0u); o2.y = MSK(v2.y, g2+1u); o2.z = MSK(v2.z, g2+2u); o2.w = MSK(v2.w, g2+3u);
            o3.x = MSK(v3.x, g3+0u); o3.y = MSK(v3.y, g3+1u); o3.z = MSK(v3.z, g3+2u); o3.w = MSK(v3.w, g3+3u);
            __stcs(&q[i], o0);
            __stcs(&q[i + bd], o1);
            __stcs(&q[i + 2 * bd], o2);
            __stcs(&q[i + 3 * bd], o3);
        }
        for (; i < end; i += bd) {
            float4 v = p[i];
            unsigned int g0 = (unsigned int)i * 4u;
            float4 o;
            o.x = MSK(v.x, g0+0u); o.y = MSK(v.y, g0+1u); o.z = MSK(v.z, g0+2u); o.w = MSK(v.w, g0+3u);
            __stcs(&q[i], o);
            #undef MSK
        }
    } else {
        for (int i = start + threadIdx.x; i < end; i += bd) {
            float4 v = p[i];
            unsigned int base = (unsigned int)i * 4u;
            unsigned int k0 = f2k(v.x), k1 = f2k(v.y), k2 = f2k(v.z), k3 = f2k(v.w);
            float4 o;
            o.x = (k0 > thrk || (k0 == thrk && base + 0u <= cut)) ? v.x : 0.0f;
            o.y = (k1 > thrk || (k1 == thrk && base + 1u <= cut)) ? v.y : 0.0f;
            o.z = (k2 > thrk || (k2 == thrk && base + 2u <= cut)) ? v.z : 0.0f;
            o.w = (k3 > thrk || (k3 == thrk && base + 3u <= cut)) ? v.w : 0.0f;
            __stcs(&q[i], o);
        }
    }
    // reset scratch for next graph replay
    if (blockIdx.x == 0 && blockIdx.y == 0) {
        if (threadIdx.x < NBATCH) {
            g_cnt[threadIdx.x] = 0;
            g_gt[threadIdx.x] = 0;
            g_arrive[threadIdx.x] = 0;
        }
        if (threadIdx.x == 0) g_fail = 0;
    }
}

// ============================== HOST =======================================

extern "C" void kernel_launch(void* const* d_in, const int* in_sizes, int n_in,
                              void* d_out, int out_size) {
    (void)n_in; (void)out_size;
    const int total = in_sizes[0];           // 33,554,432
    const int N     = total / NBATCH;        // 4,194,304
    int k = (int)((double)N * 0.1);          // 419,430
    if (k < 1) k = 1;
    const int nvec = N / 4;                  // 1,048,576 float4 per row

    const float4* in  = (const float4*)d_in[0];
    float4*       out = (float4*)d_out;

    dim3 gA(256, NBATCH);

    k_passA<<<gA, 512>>>(in, nvec, k);
    fb_all <<<NBATCH, 1024>>>(in, nvec, k);
    k_write<<<gA, 512>>>(in, out, nvec);
}

// round 8
// speedup vs baseline: 1.6803x; 1.2785x over previous
#include <cuda_runtime.h>
#include <stdint.h>

// ---------------------------------------------------------------------------
// LateralInhibition: per-batch top-k masking (B=8, N=4,194,304, k=419,430).
//
// 3 launches:
//   passA : read 128MB. 1024-thr blocks, 64 blocks/row (R2 k_cand geometry,
//           measured 38us for this scan shape). counts x>LO; stages window
//           candidates (LO<x<=HI, one uint compare). Last block per row
//           (arrive-counter) runs exact select on L2-hot candidates.
//   fb_all: gated on g_fail; fully-general exact select. ~1us early-exit.
//   write : masked write, reverse traversal + __stcs streaming stores +
//           scratch reset for next replay.
// ---------------------------------------------------------------------------

#define NBATCH 8
#define FBBINS 8192
#define CAP    262144
#define SCAP   2048
#define FINE   1024
#define MCAP   512
#define LO_F   1.26f
#define HI_F   1.31f

__device__ unsigned int g_cnt [NBATCH];     // window candidates per row
__device__ unsigned int g_gt  [NBATCH];     // count of x > LO per row
__device__ unsigned int g_arrive[NBATCH];
__device__ unsigned int g_ckey[NBATCH][CAP];
__device__ unsigned int g_cidx[NBATCH][CAP];
__device__ unsigned int g_thr [NBATCH];     // f2k key of threshold
__device__ unsigned int g_cut [NBATCH];     // max included idx among ties
__device__ int          g_fail;

// monotonic float -> uint key (larger float => larger key)
__device__ __forceinline__ unsigned int f2k(float f) {
    unsigned int u = __float_as_uint(f);
    return u ^ (0x80000000u | (unsigned int)((int)u >> 31));
}

// ============================ PASS A + SELECT ==============================

__global__ void k_passA(const float4* __restrict__ in, int nvec, int k) {
    __shared__ unsigned int skey[SCAP], sidx[SCAP];   // staging; reused by select
    __shared__ unsigned int s_n, s_base, s_gt, s_last;
    __shared__ unsigned int s_bsel, s_r, s_m, s_thr, s_extra, s_E, s_neq, s_cut;
    __shared__ unsigned int csum[32];
    const int b   = blockIdx.y;
    const int bd  = blockDim.x;
    const int tid = threadIdx.x;
    if (tid == 0) { s_n = 0; s_gt = 0; }
    __syncthreads();

    const float4* p = in + (size_t)b * nvec;
    int per_block = (nvec + gridDim.x - 1) / gridDim.x;
    int start = blockIdx.x * per_block;
    int end   = min(start + per_block, nvec);
    unsigned int mygt = 0;

    const unsigned int LOB = __float_as_uint(LO_F);
    const unsigned int WID = __float_as_uint(HI_F) - LOB;   // window width (bits)

    // Per element: mygt += (x > LO); window iff bits(x)-LOB <= WID
    // (wraps to huge for x<=LO, x<0, NaN/Inf -> single unsigned compare).
    #define PA_ELEM(x, gi) do {                                              \
        float _x = (x);                                                      \
        mygt += (_x > LO_F) ? 1u : 0u;                                       \
        if (__float_as_uint(_x) - LOB <= WID) {                              \
            unsigned int _p = atomicAdd(&s_n, 1u);                           \
            if (_p < SCAP) { skey[_p] = __float_as_uint(_x); sidx[_p] = (gi); } \
        }                                                                    \
    } while (0)

    int i = start + tid;
    for (; i + bd < end; i += 2 * bd) {
        float4 v0 = p[i];
        float4 v1 = p[i + bd];
        unsigned int g0 = (unsigned int)i * 4u;
        unsigned int g1 = (unsigned int)(i + bd) * 4u;
        PA_ELEM(v0.x, g0 + 0u); PA_ELEM(v0.y, g0 + 1u);
        PA_ELEM(v0.z, g0 + 2u); PA_ELEM(v0.w, g0 + 3u);
        PA_ELEM(v1.x, g1 + 0u); PA_ELEM(v1.y, g1 + 1u);
        PA_ELEM(v1.z, g1 + 2u); PA_ELEM(v1.w, g1 + 3u);
    }
    for (; i < end; i += bd) {
        float4 v = p[i];
        unsigned int g0 = (unsigned int)i * 4u;
        PA_ELEM(v.x, g0 + 0u); PA_ELEM(v.y, g0 + 1u);
        PA_ELEM(v.z, g0 + 2u); PA_ELEM(v.w, g0 + 3u);
    }
    #undef PA_ELEM

    #pragma unroll
    for (int o = 16; o > 0; o >>= 1) mygt += __shfl_down_sync(0xFFFFFFFFu, mygt, o);
    if ((tid & 31) == 0) atomicAdd(&s_gt, mygt);
    __syncthreads();
    if (tid == 0) {
        if (s_n > SCAP) g_fail = 1;          // staging overflow -> fallback
        unsigned int m = min(s_n, (unsigned int)SCAP);
        atomicAdd(&g_gt[b], s_gt);
        s_base = atomicAdd(&g_cnt[b], m);
        s_n = m;
    }
    __syncthreads();
    for (unsigned int j = tid; j < s_n; j += bd) {
        unsigned int gp = s_base + j;
        if (gp < CAP) { g_ckey[b][gp] = skey[j]; g_cidx[b][gp] = sidx[j]; }
    }
    __syncthreads();
    __threadfence();
    if (tid == 0)
        s_last = (atomicAdd(&g_arrive[b], 1u) == gridDim.x - 1u) ? 1u : 0u;
    __syncthreads();
    if (!s_last) return;

    // ================= last block of this row: exact select ================
    __threadfence();
    const unsigned int n  = g_cnt[b];
    const unsigned int gt = g_gt[b];
    const unsigned int uk = (unsigned int)k;
    // hi = gt - n (count strictly above window). valid window position:
    //   hi < k  <=> gt - n < k ;  hi + n >= k  <=> gt >= k
    if (!((n <= CAP) && (n <= gt) && (gt - n < uk) && (gt >= uk))) {
        if (tid == 0) g_fail = 1;
        return;
    }
    const unsigned int rank = uk - (gt - n);   // 1-based rank within window
    const unsigned int LOB2 = __float_as_uint(LO_F);
    unsigned int* h   = skey;    // reuse staging smem: h[FINE]
    unsigned int* aux = sidx;    // reuse: boundary keys / eq indices

    for (int j = tid; j < FINE; j += bd) h[j] = 0;
    if (tid == 0) { s_m = 0; s_neq = 0; s_cut = 0xFFFFFFFFu; s_thr = 0; s_extra = 0; s_E = 0; }
    __syncthreads();
    for (unsigned int j = tid; j < n; j += bd)
        atomicAdd(&h[(g_ckey[b][j] - LOB2) >> 9], 1u);
    __syncthreads();
    if (tid < 32) {
        unsigned int s = 0;
        #pragma unroll
        for (int t = 0; t < 32; t++) s += h[tid * 32 + t];
        csum[tid] = s;
    }
    __syncthreads();
    if (tid == 0) {
        unsigned int cum = 0;
        int c = 31;
        for (; c > 0; c--) {
            if (cum + csum[c] >= rank) break;
            cum += csum[c];
        }
        int bsel = c * 32;
        for (int d = c * 32 + 31; d >= c * 32; d--) {
            if (cum + h[d] >= rank) { bsel = d; break; }
            cum += h[d];
        }
        s_bsel = (unsigned int)bsel;
        s_r    = rank - cum;
    }
    __syncthreads();
    const unsigned int bsel = s_bsel, r = s_r;
    for (unsigned int j = tid; j < n; j += bd) {
        unsigned int uv = g_ckey[b][j];
        if (((uv - LOB2) >> 9) == bsel) {
            unsigned int pp = atomicAdd(&s_m, 1u);
            if (pp < MCAP) aux[pp] = uv;
        }
    }
    __syncthreads();
    unsigned int m = s_m;
    if (m > MCAP) { if (tid == 0) g_fail = 1; return; }
    for (unsigned int j = tid; j < m; j += bd) {
        unsigned int x = aux[j], cg = 0, ce = 0;
        for (unsigned int t = 0; t < m; t++) {
            unsigned int y = aux[t];
            cg += (y > x); ce += (y == x);
        }
        if (cg < r && r <= cg + ce) { s_thr = x; s_extra = r - cg; s_E = ce; }
    }
    __syncthreads();
    const unsigned int thr = s_thr, extra = s_extra, E = s_E;
    if (extra < E) {   // tie-break: extra-th smallest index among equals
        for (unsigned int j = tid; j < n; j += bd) {
            if (g_ckey[b][j] == thr) {
                unsigned int pp = atomicAdd(&s_neq, 1u);
                if (pp < SCAP) aux[pp] = g_cidx[b][j];
            }
        }
        __syncthreads();
        unsigned int ne = s_neq;
        if (ne > SCAP) { if (tid == 0) g_fail = 1; return; }
        for (unsigned int j = tid; j < ne; j += bd) {
            unsigned int me = aux[j], c2 = 0;
            for (unsigned int t = 0; t < ne; t++) c2 += (aux[t] <= me);
            if (c2 == extra) s_cut = me;
        }
        __syncthreads();
    }
    if (tid == 0) {
        g_thr[b] = thr | 0x80000000u;   // f2k of a positive float
        g_cut[b] = s_cut;
    }
}

// ================== FALLBACK: one kernel, fully general ====================

__global__ void __launch_bounds__(1024) fb_all(const float4* __restrict__ in,
                                               int nvec, int k) {
    if (!g_fail) return;
    __shared__ unsigned int sh[FBBINS];
    __shared__ unsigned int s_pref, s_krem, s_n;
    __shared__ unsigned int s_fixedval, s_fixedmask, s_rank, s_E, s_neq, s_cut;
    const int b = blockIdx.x;
    const float4* p = in + (size_t)b * nvec;
    const int bd = blockDim.x;

    for (int i = threadIdx.x; i < FBBINS; i += bd) sh[i] = 0;
    __syncthreads();
    for (int i = threadIdx.x; i < nvec; i += bd) {
        float4 v = p[i];
        atomicAdd(&sh[f2k(v.x) >> 19], 1u);
        atomicAdd(&sh[f2k(v.y) >> 19], 1u);
        atomicAdd(&sh[f2k(v.z) >> 19], 1u);
        atomicAdd(&sh[f2k(v.w) >> 19], 1u);
    }
    __syncthreads();
    if (threadIdx.x == 0) {
        unsigned int cum = 0;
        for (int j = FBBINS - 1; j >= 0; j--) {
            unsigned int c = sh[j];
            if (cum + c >= (unsigned int)k) { s_pref = (unsigned int)j; s_krem = (unsigned int)k - cum; break; }
            cum += c;
        }
        s_n = 0;
    }
    __syncthreads();
    const unsigned int pref = s_pref;
    for (int i = threadIdx.x; i < nvec; i += bd) {
        float4 v = p[i];
        unsigned int kk[4] = { f2k(v.x), f2k(v.y), f2k(v.z), f2k(v.w) };
        #pragma unroll
        for (int j = 0; j < 4; j++) {
            if ((kk[j] >> 19) == pref) {
                unsigned int pos = atomicAdd(&s_n, 1u);
                if (pos < CAP) {
                    g_ckey[b][pos] = kk[j];
                    g_cidx[b][pos] = (unsigned int)i * 4u + (unsigned int)j;
                }
            }
        }
    }
    __syncthreads();
    const unsigned int n = min(s_n, (unsigned int)CAP);
    if (threadIdx.x == 0) {
        s_fixedval = 0; s_fixedmask = 0; s_rank = s_krem; s_E = 0;
        s_neq = 0; s_cut = 0xFFFFFFFFu;
    }
    __syncthreads();
    const int shifts[3] = { 11, 3, 0 };
    const int widths[3] = { 8, 8, 3 };
    for (int r = 0; r < 3; r++) {
        const int s = shifts[r];
        const unsigned int mw = (1u << widths[r]) - 1u;
        for (int i = threadIdx.x; i < 256; i += bd) sh[i] = 0;
        __syncthreads();
        const unsigned int fm = s_fixedmask, fv = s_fixedval;
        for (unsigned int i = threadIdx.x; i < n; i += bd) {
            unsigned int low = g_ckey[b][i] & 0x7FFFFu;
            if ((low & fm) == fv) atomicAdd(&sh[(low >> s) & mw], 1u);
        }
        __syncthreads();
        if (threadIdx.x == 0) {
            unsigned int cum = 0, rank = s_rank, sel = 0;
            for (int d = (int)mw; d >= 0; d--) {
                unsigned int c = sh[d];
                if (cum + c >= rank) { sel = (unsigned int)d; s_rank = rank - cum; s_E = c; break; }
                cum += c;
            }
            s_fixedval  |= sel << s;
            s_fixedmask |= mw  << s;
        }
        __syncthreads();
    }
    const unsigned int thr   = (pref << 19) | s_fixedval;
    const unsigned int extra = s_rank;
    const unsigned int E     = s_E;
    __syncthreads();
    if (extra < E) {
        unsigned int* eq = sh;
        for (unsigned int i = threadIdx.x; i < n; i += bd) {
            if (g_ckey[b][i] == thr) {
                unsigned int pos = atomicAdd(&s_neq, 1u);
                if (pos < FBBINS) eq[pos] = g_cidx[b][i];
            }
        }
        __syncthreads();
        unsigned int ne = min(s_neq, (unsigned int)FBBINS);
        for (unsigned int j = threadIdx.x; j < ne; j += bd) {
            unsigned int me = eq[j], c = 0;
            for (unsigned int t = 0; t < ne; t++) if (eq[t] <= me) c++;
            if (c == extra) s_cut = me;
        }
        __syncthreads();
    }
    if (threadIdx.x == 0) { g_thr[b] = thr; g_cut[b] = s_cut; }
}

// ============================== WRITE ======================================

__global__ void __launch_bounds__(512) k_write(const float4* __restrict__ in,
                                               float4* __restrict__ out, int nvec) {
    const int b = blockIdx.y;
    const unsigned int thrk = g_thr[b];
    const unsigned int cut  = g_cut[b];
    const float4* p = in  + (size_t)b * nvec;
    float4*       q = out + (size_t)b * nvec;
    const int bd = blockDim.x;
    // reverse chunk order: start where passA's L2 footprint is freshest
    const int chunk = gridDim.x - 1 - blockIdx.x;
    int per_block = (nvec + gridDim.x - 1) / gridDim.x;
    int start = chunk * per_block;
    int end   = min(start + per_block, nvec);

    if (thrk > 0x80000000u) {
        const unsigned int tbits = thrk ^ 0x80000000u;
        const float tf = __uint_as_float(tbits);
        int i = start + threadIdx.x;
        for (; i + 3 * bd < end; i += 4 * bd) {
            float4 v0 = p[i];
            float4 v1 = p[i + bd];
            float4 v2 = p[i + 2 * bd];
            float4 v3 = p[i + 3 * bd];
            float4 o0, o1, o2, o3;
            unsigned int g0 = (unsigned int)i * 4u;
            unsigned int g1 = (unsigned int)(i + bd) * 4u;
            unsigned int g2 = (unsigned int)(i + 2 * bd) * 4u;
            unsigned int g3 = (unsigned int)(i + 3 * bd) * 4u;
            #define MSK(x, gi) ((x) > tf || (__float_as_uint(x) == tbits && (gi) <= cut)) ? (x) : 0.0f
            o0.x = MSK(v0.x, g0+0u); o0.y = MSK(v0.y, g0+1u); o0.z = MSK(v0.z, g0+2u); o0.w = MSK(v0.w, g0+3u);
            o1.x = MSK(v1.x, g1+0u); o1.y = MSK(v1.y, g1+1u); o1.z = MSK(v1.z, g1+2u); o1.w = MSK(v1.w, g1+3u);
            o2.x = MSK(v2.x, g2+0u); o2.y = MSK(v2.y, g2+1u); o2.z = MSK(v2.z, g2+2u); o2.w = MSK(v2.w, g2+3u);
            o3.x = MSK(v3.x, g3+0u); o3.y = MSK(v3.y, g3+1u); o3.z = MSK(v3.z, g3+2u); o3.w = MSK(v3.w, g3+3u);
            __stcs(&q[i], o0);
            __stcs(&q[i + bd], o1);
            __stcs(&q[i + 2 * bd], o2);
            __stcs(&q[i + 3 * bd], o3);
        }
        for (; i < end; i += bd) {
            float4 v = p[i];
            unsigned int g0 = (unsigned int)i * 4u;
            float4 o;
            o.x = MSK(v.x, g0+0u); o.y = MSK(v.y, g0+1u); o.z = MSK(v.z, g0+2u); o.w = MSK(v.w, g0+3u);
            __stcs(&q[i], o);
            #undef MSK
        }
    } else {
        for (int i = start + threadIdx.x; i < end; i += bd) {
            float4 v = p[i];
            unsigned int base = (unsigned int)i * 4u;
            unsigned int k0 = f2k(v.x), k1 = f2k(v.y), k2 = f2k(v.z), k3 = f2k(v.w);
            float4 o;
            o.x = (k0 > thrk || (k0 == thrk && base + 0u <= cut)) ? v.x : 0.0f;
            o.y = (k1 > thrk || (k1 == thrk && base + 1u <= cut)) ? v.y : 0.0f;
            o.z = (k2 > thrk || (k2 == thrk && base + 2u <= cut)) ? v.z : 0.0f;
            o.w = (k3 > thrk || (k3 == thrk && base + 3u <= cut)) ? v.w : 0.0f;
            __stcs(&q[i], o);
        }
    }
    // reset scratch for next graph replay
    if (blockIdx.x == 0 && blockIdx.y == 0) {
        if (threadIdx.x < NBATCH) {
            g_cnt[threadIdx.x] = 0;
            g_gt[threadIdx.x] = 0;
            g_arrive[threadIdx.x] = 0;
        }
        if (threadIdx.x == 0) g_fail = 0;
    }
}

// ============================== HOST =======================================

extern "C" void kernel_launch(void* const* d_in, const int* in_sizes, int n_in,
                              void* d_out, int out_size) {
    (void)n_in; (void)out_size;
    const int total = in_sizes[0];           // 33,554,432
    const int N     = total / NBATCH;        // 4,194,304
    int k = (int)((double)N * 0.1);          // 419,430
    if (k < 1) k = 1;
    const int nvec = N / 4;                  // 1,048,576 float4 per row

    const float4* in  = (const float4*)d_in[0];
    float4*       out = (float4*)d_out;

    dim3 gA(64, NBATCH);                     // R2 k_cand geometry
    dim3 gW(256, NBATCH);

    k_passA<<<gA, 1024>>>(in, nvec, k);
    fb_all <<<NBATCH, 1024>>>(in, nvec, k);
    k_write<<<gW, 512>>>(in, out, nvec);
}

// round 9
// speedup vs baseline: 1.7280x; 1.0284x over previous
#include <cuda_runtime.h>
#include <stdint.h>

// ---------------------------------------------------------------------------
// LateralInhibition: per-batch top-k masking (B=8, N=4,194,304, k=419,430).
//
// 3 launches:
//   passA : read 128MB, 1024-thr blocks x 64 blocks/row, unroll-4.
//           Branchless integer-predicate count of x>LO; ONE branch per
//           float4 (umin trick) guards rare window pushes (LO<x<=HI,
//           ~14.7K/row). Last block per row runs exact select on L2-hot
//           candidates: 1024-bin hist -> threshold + tie cutoff.
//   fb_all: gated on g_fail; fully-general exact select. ~1us early-exit.
//   write : masked write, reverse traversal + __stcs streaming stores +
//           scratch reset for next replay.
// ---------------------------------------------------------------------------

#define NBATCH 8
#define FBBINS 8192
#define CAP    262144
#define SCAP   2048
#define FINE   1024
#define MCAP   512
#define LO_F   1.272f       // window: +-11 sigma around thr ~ 1.2816+-0.00084
#define HI_F   1.292f

__device__ unsigned int g_cnt [NBATCH];     // window candidates per row
__device__ unsigned int g_gt  [NBATCH];     // count of x >= LO per row
__device__ unsigned int g_arrive[NBATCH];
__device__ unsigned int g_ckey[NBATCH][CAP];
__device__ unsigned int g_cidx[NBATCH][CAP];
__device__ unsigned int g_thr [NBATCH];     // f2k key of threshold
__device__ unsigned int g_cut [NBATCH];     // max included idx among ties
__device__ int          g_fail;

// monotonic float -> uint key (larger float => larger key)
__device__ __forceinline__ unsigned int f2k(float f) {
    unsigned int u = __float_as_uint(f);
    return u ^ (0x80000000u | (unsigned int)((int)u >> 31));
}

// ============================ PASS A + SELECT ==============================

__global__ void k_passA(const float4* __restrict__ in, int nvec, int k) {
    __shared__ unsigned int skey[SCAP], sidx[SCAP];   // staging; reused by select
    __shared__ unsigned int s_n, s_base, s_gt, s_last;
    __shared__ unsigned int s_bsel, s_r, s_m, s_thr, s_extra, s_E, s_neq, s_cut;
    __shared__ unsigned int csum[32];
    const int b   = blockIdx.y;
    const int bd  = blockDim.x;
    const int tid = threadIdx.x;
    if (tid == 0) { s_n = 0; s_gt = 0; }
    __syncthreads();

    const float4* p = in + (size_t)b * nvec;
    int per_block = (nvec + gridDim.x - 1) / gridDim.x;
    int start = blockIdx.x * per_block;
    int end   = min(start + per_block, nvec);
    unsigned int mygt = 0;

    const unsigned int LOB = __float_as_uint(LO_F);
    const unsigned int WID = __float_as_uint(HI_F) - LOB;   // window width (bits)
    const unsigned int GTW = 0x7F800000u - LOB;             // [LO, +inf] width
    // t = bits(x)-LOB:  t<=GTW <=> x in [LO,+inf] (negatives/NaN wrap huge);
    //                   t<=WID <=> x in [LO,HI]   (window; candidate push)
    // LO-boundary elements appear in BOTH gt and n consistently, so
    // hi = gt - n (count above window) is exact.

    #define PA_VEC(v, vi) do {                                               \
        unsigned int t0 = __float_as_uint((v).x) - LOB;                      \
        unsigned int t1 = __float_as_uint((v).y) - LOB;                      \
        unsigned int t2 = __float_as_uint((v).z) - LOB;                      \
        unsigned int t3 = __float_as_uint((v).w) - LOB;                      \
        mygt += (t0 <= GTW) ? 1u : 0u;                                       \
        mygt += (t1 <= GTW) ? 1u : 0u;                                       \
        mygt += (t2 <= GTW) ? 1u : 0u;                                       \
        mygt += (t3 <= GTW) ? 1u : 0u;                                       \
        unsigned int mm = umin(umin(t0, t1), umin(t2, t3));                  \
        if (mm <= WID) {                                                     \
            unsigned int gb = (unsigned int)(vi) * 4u;                       \
            if (t0 <= WID) { unsigned int _p = atomicAdd(&s_n, 1u);          \
                if (_p < SCAP) { skey[_p] = t0 + LOB; sidx[_p] = gb; } }     \
            if (t1 <= WID) { unsigned int _p = atomicAdd(&s_n, 1u);          \
                if (_p < SCAP) { skey[_p] = t1 + LOB; sidx[_p] = gb + 1u; } }\
            if (t2 <= WID) { unsigned int _p = atomicAdd(&s_n, 1u);          \
                if (_p < SCAP) { skey[_p] = t2 + LOB; sidx[_p] = gb + 2u; } }\
            if (t3 <= WID) { unsigned int _p = atomicAdd(&s_n, 1u);          \
                if (_p < SCAP) { skey[_p] = t3 + LOB; sidx[_p] = gb + 3u; } }\
        }                                                                    \
    } while (0)

    int i = start + tid;
    for (; i + 3 * bd < end; i += 4 * bd) {
        float4 v0 = p[i];
        float4 v1 = p[i + bd];
        float4 v2 = p[i + 2 * bd];
        float4 v3 = p[i + 3 * bd];
        PA_VEC(v0, i);
        PA_VEC(v1, i + bd);
        PA_VEC(v2, i + 2 * bd);
        PA_VEC(v3, i + 3 * bd);
    }
    for (; i < end; i += bd) {
        float4 v = p[i];
        PA_VEC(v, i);
    }
    #undef PA_VEC

    #pragma unroll
    for (int o = 16; o > 0; o >>= 1) mygt += __shfl_down_sync(0xFFFFFFFFu, mygt, o);
    if ((tid & 31) == 0) atomicAdd(&s_gt, mygt);
    __syncthreads();
    if (tid == 0) {
        if (s_n > SCAP) g_fail = 1;          // staging overflow -> fallback
        unsigned int m = min(s_n, (unsigned int)SCAP);
        atomicAdd(&g_gt[b], s_gt);
        s_base = atomicAdd(&g_cnt[b], m);
        s_n = m;
    }
    __syncthreads();
    for (unsigned int j = tid; j < s_n; j += bd) {
        unsigned int gp = s_base + j;
        if (gp < CAP) { g_ckey[b][gp] = skey[j]; g_cidx[b][gp] = sidx[j]; }
    }
    __syncthreads();
    __threadfence();
    if (tid == 0)
        s_last = (atomicAdd(&g_arrive[b], 1u) == gridDim.x - 1u) ? 1u : 0u;
    __syncthreads();
    if (!s_last) return;

    // ================= last block of this row: exact select ================
    __threadfence();
    const unsigned int n  = g_cnt[b];
    const unsigned int gt = g_gt[b];
    const unsigned int uk = (unsigned int)k;
    // hi = gt - n (count strictly above window). valid window position:
    //   hi < k  <=> gt - n < k ;  hi + n >= k  <=> gt >= k
    if (!((n <= CAP) && (n <= gt) && (gt - n < uk) && (gt >= uk))) {
        if (tid == 0) g_fail = 1;
        return;
    }
    const unsigned int rank = uk - (gt - n);   // 1-based rank within window
    const unsigned int LOB2 = __float_as_uint(LO_F);
    unsigned int* h   = skey;    // reuse staging smem: h[FINE]
    unsigned int* aux = sidx;    // reuse: boundary keys / eq indices

    for (int j = tid; j < FINE; j += bd) h[j] = 0;
    if (tid == 0) { s_m = 0; s_neq = 0; s_cut = 0xFFFFFFFFu; s_thr = 0; s_extra = 0; s_E = 0; }
    __syncthreads();
    for (unsigned int j = tid; j < n; j += bd)
        atomicAdd(&h[(g_ckey[b][j] - LOB2) >> 9], 1u);
    __syncthreads();
    if (tid < 32) {
        unsigned int s = 0;
        #pragma unroll
        for (int t = 0; t < 32; t++) s += h[tid * 32 + t];
        csum[tid] = s;
    }
    __syncthreads();
    if (tid == 0) {
        unsigned int cum = 0;
        int c = 31;
        for (; c > 0; c--) {
            if (cum + csum[c] >= rank) break;
            cum += csum[c];
        }
        int bsel = c * 32;
        for (int d = c * 32 + 31; d >= c * 32; d--) {
            if (cum + h[d] >= rank) { bsel = d; break; }
            cum += h[d];
        }
        s_bsel = (unsigned int)bsel;
        s_r    = rank - cum;
    }
    __syncthreads();
    const unsigned int bsel = s_bsel, r = s_r;
    for (unsigned int j = tid; j < n; j += bd) {
        unsigned int uv = g_ckey[b][j];
        if (((uv - LOB2) >> 9) == bsel) {
            unsigned int pp = atomicAdd(&s_m, 1u);
            if (pp < MCAP) aux[pp] = uv;
        }
    }
    __syncthreads();
    unsigned int m = s_m;
    if (m > MCAP) { if (tid == 0) g_fail = 1; return; }
    for (unsigned int j = tid; j < m; j += bd) {
        unsigned int x = aux[j], cg = 0, ce = 0;
        for (unsigned int t = 0; t < m; t++) {
            unsigned int y = aux[t];
            cg += (y > x); ce += (y == x);
        }
        if (cg < r && r <= cg + ce) { s_thr = x; s_extra = r - cg; s_E = ce; }
    }
    __syncthreads();
    const unsigned int thr = s_thr, extra = s_extra, E = s_E;
    if (extra < E) {   // tie-break: extra-th smallest index among equals
        for (unsigned int j = tid; j < n; j += bd) {
            if (g_ckey[b][j] == thr) {
                unsigned int pp = atomicAdd(&s_neq, 1u);
                if (pp < SCAP) aux[pp] = g_cidx[b][j];
            }
        }
        __syncthreads();
        unsigned int ne = s_neq;
        if (ne > SCAP) { if (tid == 0) g_fail = 1; return; }
        for (unsigned int j = tid; j < ne; j += bd) {
            unsigned int me = aux[j], c2 = 0;
            for (unsigned int t = 0; t < ne; t++) c2 += (aux[t] <= me);
            if (c2 == extra) s_cut = me;
        }
        __syncthreads();
    }
    if (tid == 0) {
        g_thr[b] = thr | 0x80000000u;   // f2k of a positive float
        g_cut[b] = s_cut;
    }
}

// ================== FALLBACK: one kernel, fully general ====================

__global__ void __launch_bounds__(1024) fb_all(const float4* __restrict__ in,
                                               int nvec, int k) {
    if (!g_fail) return;
    __shared__ unsigned int sh[FBBINS];
    __shared__ unsigned int s_pref, s_krem, s_n;
    __shared__ unsigned int s_fixedval, s_fixedmask, s_rank, s_E, s_neq, s_cut;
    const int b = blockIdx.x;
    const float4* p = in + (size_t)b * nvec;
    const int bd = blockDim.x;

    for (int i = threadIdx.x; i < FBBINS; i += bd) sh[i] = 0;
    __syncthreads();
    for (int i = threadIdx.x; i < nvec; i += bd) {
        float4 v = p[i];
        atomicAdd(&sh[f2k(v.x) >> 19], 1u);
        atomicAdd(&sh[f2k(v.y) >> 19], 1u);
        atomicAdd(&sh[f2k(v.z) >> 19], 1u);
        atomicAdd(&sh[f2k(v.w) >> 19], 1u);
    }
    __syncthreads();
    if (threadIdx.x == 0) {
        unsigned int cum = 0;
        for (int j = FBBINS - 1; j >= 0; j--) {
            unsigned int c = sh[j];
            if (cum + c >= (unsigned int)k) { s_pref = (unsigned int)j; s_krem = (unsigned int)k - cum; break; }
            cum += c;
        }
        s_n = 0;
    }
    __syncthreads();
    const unsigned int pref = s_pref;
    for (int i = threadIdx.x; i < nvec; i += bd) {
        float4 v = p[i];
        unsigned int kk[4] = { f2k(v.x), f2k(v.y), f2k(v.z), f2k(v.w) };
        #pragma unroll
        for (int j = 0; j < 4; j++) {
            if ((kk[j] >> 19) == pref) {
                unsigned int pos = atomicAdd(&s_n, 1u);
                if (pos < CAP) {
                    g_ckey[b][pos] = kk[j];
                    g_cidx[b][pos] = (unsigned int)i * 4u + (unsigned int)j;
                }
            }
        }
    }
    __syncthreads();
    const unsigned int n = min(s_n, (unsigned int)CAP);
    if (threadIdx.x == 0) {
        s_fixedval = 0; s_fixedmask = 0; s_rank = s_krem; s_E = 0;
        s_neq = 0; s_cut = 0xFFFFFFFFu;
    }
    __syncthreads();
    const int shifts[3] = { 11, 3, 0 };
    const int widths[3] = { 8, 8, 3 };
    for (int r = 0; r < 3; r++) {
        const int s = shifts[r];
        const unsigned int mw = (1u << widths[r]) - 1u;
        for (int i = threadIdx.x; i < 256; i += bd) sh[i] = 0;
        __syncthreads();
        const unsigned int fm = s_fixedmask, fv = s_fixedval;
        for (unsigned int i = threadIdx.x; i < n; i += bd) {
            unsigned int low = g_ckey[b][i] & 0x7FFFFu;
            if ((low & fm) == fv) atomicAdd(&sh[(low >> s) & mw], 1u);
        }
        __syncthreads();
        if (threadIdx.x == 0) {
            unsigned int cum = 0, rank = s_rank, sel = 0;
            for (int d = (int)mw; d >= 0; d--) {
                unsigned int c = sh[d];
                if (cum + c >= rank) { sel = (unsigned int)d; s_rank = rank - cum; s_E = c; break; }
                cum += c;
            }
            s_fixedval  |= sel << s;
            s_fixedmask |= mw  << s;
        }
        __syncthreads();
    }
    const unsigned int thr   = (pref << 19) | s_fixedval;
    const unsigned int extra = s_rank;
    const unsigned int E     = s_E;
    __syncthreads();
    if (extra < E) {
        unsigned int* eq = sh;
        for (unsigned int i = threadIdx.x; i < n; i += bd) {
            if (g_ckey[b][i] == thr) {
                unsigned int pos = atomicAdd(&s_neq, 1u);
                if (pos < FBBINS) eq[pos] = g_cidx[b][i];
            }
        }
        __syncthreads();
        unsigned int ne = min(s_neq, (unsigned int)FBBINS);
        for (unsigned int j = threadIdx.x; j < ne; j += bd) {
            unsigned int me = eq[j], c = 0;
            for (unsigned int t = 0; t < ne; t++) if (eq[t] <= me) c++;
            if (c == extra) s_cut = me;
        }
        __syncthreads();
    }
    if (threadIdx.x == 0) { g_thr[b] = thr; g_cut[b] = s_cut; }
}

// ============================== WRITE ======================================

__global__ void __launch_bounds__(512) k_write(const float4* __restrict__ in,
                                               float4* __restrict__ out, int nvec) {
    const int b = blockIdx.y;
    const unsigned int thrk = g_thr[b];
    const unsigned int cut  = g_cut[b];
    const float4* p = in  + (size_t)b * nvec;
    float4*       q = out + (size_t)b * nvec;
    const int bd = blockDim.x;
    // reverse chunk order: start where passA's L2 footprint is freshest
    const int chunk = gridDim.x - 1 - blockIdx.x;
    int per_block = (nvec + gridDim.x - 1) / gridDim.x;
    int start = chunk * per_block;
    int end   = min(start + per_block, nvec);

    if (thrk > 0x80000000u) {
        const unsigned int tbits = thrk ^ 0x80000000u;
        const float tf = __uint_as_float(tbits);
        int i = start + threadIdx.x;
        for (; i + 3 * bd < end; i += 4 * bd) {
            float4 v0 = p[i];
            float4 v1 = p[i + bd];
            float4 v2 = p[i + 2 * bd];
            float4 v3 = p[i + 3 * bd];
            float4 o0, o1, o2, o3;
            unsigned int g0 = (unsigned int)i * 4u;
            unsigned int g1 = (unsigned int)(i + bd) * 4u;
            unsigned int g2 = (unsigned int)(i + 2 * bd) * 4u;
            unsigned int g3 = (unsigned int)(i + 3 * bd) * 4u;
            #define MSK(x, gi) ((x) > tf || (__float_as_uint(x) == tbits && (gi) <= cut)) ? (x) : 0.0f
            o0.x = MSK(v0.x, g0+0u); o0.y = MSK(v0.y, g0+1u); o0.z = MSK(v0.z, g0+2u); o0.w = MSK(v0.w, g0+3u);
            o1.x = MSK(v1.x, g1+0u); o1.y = MSK(v1.y, g1+1u); o1.z = MSK(v1.z, g1+2u); o1.w = MSK(v1.w, g1+3u);
            o2.x = MSK(v2.x, g2+0u); o2.y = MSK(v2.y, g2+1u); o2.z = MSK(v2.z, g2+2u); o2.w = MSK(v2.w, g2+3u);
            o3.x = MSK(v3.x, g3+0u); o3.y = MSK(v3.y, g3+1u); o3.z = MSK(v3.z, g3+2u); o3.w = MSK(v3.w, g3+3u);
            __stcs(&q[i], o0);
            __stcs(&q[i + bd], o1);
            __stcs(&q[i + 2 * bd], o2);
            __stcs(&q[i + 3 * bd], o3);
        }
        for (; i < end; i += bd) {
            float4 v = p[i];
            unsigned int g0 = (unsigned int)i * 4u;
            float4 o;
            o.x = MSK(v.x, g0+0u); o.y = MSK(v.y, g0+1u); o.z = MSK(v.z, g0+2u); o.w = MSK(v.w, g0+3u);
            __stcs(&q[i], o);
            #undef MSK
        }
    } else {
        for (int i = start + threadIdx.x; i < end; i += bd) {
            float4 v = p[i];
            unsigned int base = (unsigned int)i * 4u;
            unsigned int k0 = f2k(v.x), k1 = f2k(v.y), k2 = f2k(v.z), k3 = f2k(v.w);
            float4 o;
            o.x = (k0 > thrk || (k0 == thrk && base + 0u <= cut)) ? v.x : 0.0f;
            o.y = (k1 > thrk || (k1 == thrk && base + 1u <= cut)) ? v.y : 0.0f;
            o.z = (k2 > thrk || (k2 == thrk && base + 2u <= cut)) ? v.z : 0.0f;
            o.w = (k3 > thrk || (k3 == thrk && base + 3u <= cut)) ? v.w : 0.0f;
            __stcs(&q[i], o);
        }
    }
    // reset scratch for next graph replay
    if (blockIdx.x == 0 && blockIdx.y == 0) {
        if (threadIdx.x < NBATCH) {
            g_cnt[threadIdx.x] = 0;
            g_gt[threadIdx.x] = 0;
            g_arrive[threadIdx.x] = 0;
        }
        if (threadIdx.x == 0) g_fail = 0;
    }
}

// ============================== HOST =======================================

extern "C" void kernel_launch(void* const* d_in, const int* in_sizes, int n_in,
                              void* d_out, int out_size) {
    (void)n_in; (void)out_size;
    const int total = in_sizes[0];           // 33,554,432
    const int N     = total / NBATCH;        // 4,194,304
    int k = (int)((double)N * 0.1);          // 419,430
    if (k < 1) k = 1;
    const int nvec = N / 4;                  // 1,048,576 float4 per row

    const float4* in  = (const float4*)d_in[0];
    float4*       out = (float4*)d_out;

    dim3 gA(64, NBATCH);
    dim3 gW(256, NBATCH);

    k_passA<<<gA, 1024>>>(in, nvec, k);
    fb_all <<<NBATCH, 1024>>>(in, nvec, k);
    k_write<<<gW, 512>>>(in, out, nvec);
}

// round 11
// speedup vs baseline: 1.7525x; 1.0142x over previous
#include <cuda_runtime.h>
#include <stdint.h>

// ---------------------------------------------------------------------------
// LateralInhibition: per-batch top-k masking (B=8, N=4,194,304, k=419,430).
//
// 3 launches:
//   passA : read 128MB, 512-thr blocks x 128 blocks/row, unroll-4 (MLP-4),
//           __launch_bounds__(512,3) -> 75% occupancy at <=42 regs.
//           Branchless integer-predicate count of x>=LO; ONE branch per
//           float4 (umin trick) guards rare window pushes (LO<=x<=HI,
//           ~14.7K/row). Last block per row runs exact select on L2-hot
//           candidates: fine hist -> threshold + tie cutoff.
//   fb_all: gated on g_fail; fully-general exact select. ~1us early-exit.
//   write : masked write, reverse traversal + __stcs streaming stores +
//           scratch reset for next replay.
// ---------------------------------------------------------------------------

#define NBATCH 8
#define FBBINS 8192
#define CAP    262144
#define SCAP   1024
#define FINE   1024
#define MCAP   512
#define LO_F   1.272f       // window: +-11 sigma around thr ~ 1.2816+-0.00084
#define HI_F   1.292f

__device__ unsigned int g_cnt [NBATCH];     // window candidates per row
__device__ unsigned int g_gt  [NBATCH];     // count of x >= LO per row
__device__ unsigned int g_arrive[NBATCH];
__device__ unsigned int g_ckey[NBATCH][CAP];
__device__ unsigned int g_cidx[NBATCH][CAP];
__device__ unsigned int g_thr [NBATCH];     // f2k key of threshold
__device__ unsigned int g_cut [NBATCH];     // max included idx among ties
__device__ int          g_fail;

// monotonic float -> uint key (larger float => larger key)
__device__ __forceinline__ unsigned int f2k(float f) {
    unsigned int u = __float_as_uint(f);
    return u ^ (0x80000000u | (unsigned int)((int)u >> 31));
}

// ============================ PASS A + SELECT ==============================

__global__ void __launch_bounds__(512, 3)
k_passA(const float4* __restrict__ in, int nvec, int k) {
    __shared__ unsigned int skey[SCAP], sidx[SCAP];   // staging; reused by select
    __shared__ unsigned int s_n, s_base, s_gt, s_last;
    __shared__ unsigned int s_bsel, s_r, s_m, s_thr, s_extra, s_E, s_neq, s_cut;
    __shared__ unsigned int csum[32];
    const int b   = blockIdx.y;
    const int bd  = blockDim.x;
    const int tid = threadIdx.x;
    if (tid == 0) { s_n = 0; s_gt = 0; }
    __syncthreads();

    const float4* p = in + (size_t)b * nvec;
    int per_block = (nvec + gridDim.x - 1) / gridDim.x;
    int start = blockIdx.x * per_block;
    int end   = min(start + per_block, nvec);
    unsigned int mygt = 0;

    const unsigned int LOB = __float_as_uint(LO_F);
    const unsigned int WID = __float_as_uint(HI_F) - LOB;   // window width (bits)
    const unsigned int GTW = 0x7F800000u - LOB;             // [LO, +inf] width
    // t = bits(x)-LOB:  t<=GTW <=> x in [LO,+inf] (negatives/NaN wrap huge);
    //                   t<=WID <=> x in [LO,HI]   (window; candidate push)
    // LO-boundary elements appear in BOTH gt and n consistently, so
    // hi = gt - n (count above window) is exact.

    #define PA_VEC(v, vi) do {                                               \
        unsigned int t0 = __float_as_uint((v).x) - LOB;                      \
        unsigned int t1 = __float_as_uint((v).y) - LOB;                      \
        unsigned int t2 = __float_as_uint((v).z) - LOB;                      \
        unsigned int t3 = __float_as_uint((v).w) - LOB;                      \
        mygt += (t0 <= GTW) ? 1u : 0u;                                       \
        mygt += (t1 <= GTW) ? 1u : 0u;                                       \
        mygt += (t2 <= GTW) ? 1u : 0u;                                       \
        mygt += (t3 <= GTW) ? 1u : 0u;                                       \
        unsigned int mm = umin(umin(t0, t1), umin(t2, t3));                  \
        if (mm <= WID) {                                                     \
            unsigned int gb = (unsigned int)(vi) * 4u;                       \
            if (t0 <= WID) { unsigned int _p = atomicAdd(&s_n, 1u);          \
                if (_p < SCAP) { skey[_p] = t0 + LOB; sidx[_p] = gb; } }     \
            if (t1 <= WID) { unsigned int _p = atomicAdd(&s_n, 1u);          \
                if (_p < SCAP) { skey[_p] = t1 + LOB; sidx[_p] = gb + 1u; } }\
            if (t2 <= WID) { unsigned int _p = atomicAdd(&s_n, 1u);          \
                if (_p < SCAP) { skey[_p] = t2 + LOB; sidx[_p] = gb + 2u; } }\
            if (t3 <= WID) { unsigned int _p = atomicAdd(&s_n, 1u);          \
                if (_p < SCAP) { skey[_p] = t3 + LOB; sidx[_p] = gb + 3u; } }\
        }                                                                    \
    } while (0)

    int i = start + tid;
    for (; i + 3 * bd < end; i += 4 * bd) {
        float4 v0 = p[i];
        float4 v1 = p[i + bd];
        float4 v2 = p[i + 2 * bd];
        float4 v3 = p[i + 3 * bd];
        PA_VEC(v0, i);
        PA_VEC(v1, i + bd);
        PA_VEC(v2, i + 2 * bd);
        PA_VEC(v3, i + 3 * bd);
    }
    for (; i < end; i += bd) {
        float4 v = p[i];
        PA_VEC(v, i);
    }
    #undef PA_VEC

    #pragma unroll
    for (int o = 16; o > 0; o >>= 1) mygt += __shfl_down_sync(0xFFFFFFFFu, mygt, o);
    if ((tid & 31) == 0) atomicAdd(&s_gt, mygt);
    __syncthreads();
    if (tid == 0) {
        if (s_n > SCAP) g_fail = 1;          // staging overflow -> fallback
        unsigned int m = min(s_n, (unsigned int)SCAP);
        atomicAdd(&g_gt[b], s_gt);
        s_base = atomicAdd(&g_cnt[b], m);
        s_n = m;
    }
    __syncthreads();
    for (unsigned int j = tid; j < s_n; j += bd) {
        unsigned int gp = s_base + j;
        if (gp < CAP) { g_ckey[b][gp] = skey[j]; g_cidx[b][gp] = sidx[j]; }
    }
    __syncthreads();
    __threadfence();
    if (tid == 0)
        s_last = (atomicAdd(&g_arrive[b], 1u) == gridDim.x - 1u) ? 1u : 0u;
    __syncthreads();
    if (!s_last) return;

    // ================= last block of this row: exact select ================
    __threadfence();
    const unsigned int n  = g_cnt[b];
    const unsigned int gt = g_gt[b];
    const unsigned int uk = (unsigned int)k;
    // hi = gt - n (count strictly above window). valid window position:
    //   hi < k  <=> gt - n < k ;  hi + n >= k  <=> gt >= k
    if (!((n <= CAP) && (n <= gt) && (gt - n < uk) && (gt >= uk))) {
        if (tid == 0) g_fail = 1;
        return;
    }
    const unsigned int rank = uk - (gt - n);   // 1-based rank within window
    const unsigned int LOB2 = __float_as_uint(LO_F);
    unsigned int* h   = skey;    // reuse staging smem: h[FINE]
    unsigned int* aux = sidx;    // reuse: boundary keys / eq indices

    for (int j = tid; j < FINE; j += bd) h[j] = 0;
    if (tid == 0) { s_m = 0; s_neq = 0; s_cut = 0xFFFFFFFFu; s_thr = 0; s_extra = 0; s_E = 0; }
    __syncthreads();
    // fine bins: window bit-span = bits(HI)-bits(LO) ~ 0x2A000; >>8 gives
    // 256-ulp bins, max ~672 bins <= FINE=1024.
    for (unsigned int j = tid; j < n; j += bd)
        atomicAdd(&h[(g_ckey[b][j] - LOB2) >> 8], 1u);
    __syncthreads();
    if (tid < 32) {
        unsigned int s = 0;
        #pragma unroll
        for (int t = 0; t < 32; t++) s += h[tid * 32 + t];
        csum[tid] = s;
    }
    __syncthreads();
    if (tid == 0) {
        unsigned int cum = 0;
        int c = 31;
        for (; c > 0; c--) {
            if (cum + csum[c] >= rank) break;
            cum += csum[c];
        }
        int bsel = c * 32;
        for (int d = c * 32 + 31; d >= c * 32; d--) {
            if (cum + h[d] >= rank) { bsel = d; break; }
            cum += h[d];
        }
        s_bsel = (unsigned int)bsel;
        s_r    = rank - cum;
    }
    __syncthreads();
    const unsigned int bsel = s_bsel, r = s_r;
    for (unsigned int j = tid; j < n; j += bd) {
        unsigned int uv = g_ckey[b][j];
        if (((uv - LOB2) >> 8) == bsel) {
            unsigned int pp = atomicAdd(&s_m, 1u);
            if (pp < MCAP) aux[pp] = uv;
        }
    }
    __syncthreads();
    unsigned int m = s_m;
    if (m > MCAP) { if (tid == 0) g_fail = 1; return; }
    for (unsigned int j = tid; j < m; j += bd) {
        unsigned int x = aux[j], cg = 0, ce = 0;
        for (unsigned int t = 0; t < m; t++) {
            unsigned int y = aux[t];
            cg += (y > x); ce += (y == x);
        }
        if (cg < r && r <= cg + ce) { s_thr = x; s_extra = r - cg; s_E = ce; }
    }
    __syncthreads();
    const unsigned int thr = s_thr, extra = s_extra, E = s_E;
    if (extra < E) {   // tie-break: extra-th smallest index among equals
        for (unsigned int j = tid; j < n; j += bd) {
            if (g_ckey[b][j] == thr) {
                unsigned int pp = atomicAdd(&s_neq, 1u);
                if (pp < SCAP) aux[pp] = g_cidx[b][j];
            }
        }
        __syncthreads();
        unsigned int ne = s_neq;
        if (ne > SCAP) { if (tid == 0) g_fail = 1; return; }
        for (unsigned int j = tid; j < ne; j += bd) {
            unsigned int me = aux[j], c2 = 0;
            for (unsigned int t = 0; t < ne; t++) c2 += (aux[t] <= me);
            if (c2 == extra) s_cut = me;
        }
        __syncthreads();
    }
    if (tid == 0) {
        g_thr[b] = thr | 0x80000000u;   // f2k of a positive float
        g_cut[b] = s_cut;
    }
}

// ================== FALLBACK: one kernel, fully general ====================

__global__ void __launch_bounds__(1024) fb_all(const float4* __restrict__ in,
                                               int nvec, int k) {
    if (!g_fail) return;
    __shared__ unsigned int sh[FBBINS];
    __shared__ unsigned int s_pref, s_krem, s_n;
    __shared__ unsigned int s_fixedval, s_fixedmask, s_rank, s_E, s_neq, s_cut;
    const int b = blockIdx.x;
    const float4* p = in + (size_t)b * nvec;
    const int bd = blockDim.x;

    for (int i = threadIdx.x; i < FBBINS; i += bd) sh[i] = 0;
    __syncthreads();
    for (int i = threadIdx.x; i < nvec; i += bd) {
        float4 v = p[i];
        atomicAdd(&sh[f2k(v.x) >> 19], 1u);
        atomicAdd(&sh[f2k(v.y) >> 19], 1u);
        atomicAdd(&sh[f2k(v.z) >> 19], 1u);
        atomicAdd(&sh[f2k(v.w) >> 19], 1u);
    }
    __syncthreads();
    if (threadIdx.x == 0) {
        unsigned int cum = 0;
        for (int j = FBBINS - 1; j >= 0; j--) {
            unsigned int c = sh[j];
            if (cum + c >= (unsigned int)k) { s_pref = (unsigned int)j; s_krem = (unsigned int)k - cum; break; }
            cum += c;
        }
        s_n = 0;
    }
    __syncthreads();
    const unsigned int pref = s_pref;
    for (int i = threadIdx.x; i < nvec; i += bd) {
        float4 v = p[i];
        unsigned int kk[4] = { f2k(v.x), f2k(v.y), f2k(v.z), f2k(v.w) };
        #pragma unroll
        for (int j = 0; j < 4; j++) {
            if ((kk[j] >> 19) == pref) {
                unsigned int pos = atomicAdd(&s_n, 1u);
                if (pos < CAP) {
                    g_ckey[b][pos] = kk[j];
                    g_cidx[b][pos] = (unsigned int)i * 4u + (unsigned int)j;
                }
            }
        }
    }
    __syncthreads();
    const unsigned int n = min(s_n, (unsigned int)CAP);
    if (threadIdx.x == 0) {
        s_fixedval = 0; s_fixedmask = 0; s_rank = s_krem; s_E = 0;
        s_neq = 0; s_cut = 0xFFFFFFFFu;
    }
    __syncthreads();
    const int shifts[3] = { 11, 3, 0 };
    const int widths[3] = { 8, 8, 3 };
    for (int r = 0; r < 3; r++) {
        const int s = shifts[r];
        const unsigned int mw = (1u << widths[r]) - 1u;
        for (int i = threadIdx.x; i < 256; i += bd) sh[i] = 0;
        __syncthreads();
        const unsigned int fm = s_fixedmask, fv = s_fixedval;
        for (unsigned int i = threadIdx.x; i < n; i += bd) {
            unsigned int low = g_ckey[b][i] & 0x7FFFFu;
            if ((low & fm) == fv) atomicAdd(&sh[(low >> s) & mw], 1u);
        }
        __syncthreads();
        if (threadIdx.x == 0) {
            unsigned int cum = 0, rank = s_rank, sel = 0;
            for (int d = (int)mw; d >= 0; d--) {
                unsigned int c = sh[d];
                if (cum + c >= rank) { sel = (unsigned int)d; s_rank = rank - cum; s_E = c; break; }
                cum += c;
            }
            s_fixedval  |= sel << s;
            s_fixedmask |= mw  << s;
        }
        __syncthreads();
    }
    const unsigned int thr   = (pref << 19) | s_fixedval;
    const unsigned int extra = s_rank;
    const unsigned int E     = s_E;
    __syncthreads();
    if (extra < E) {
        unsigned int* eq = sh;
        for (unsigned int i = threadIdx.x; i < n; i += bd) {
            if (g_ckey[b][i] == thr) {
                unsigned int pos = atomicAdd(&s_neq, 1u);
                if (pos < FBBINS) eq[pos] = g_cidx[b][i];
            }
        }
        __syncthreads();
        unsigned int ne = min(s_neq, (unsigned int)FBBINS);
        for (unsigned int j = threadIdx.x; j < ne; j += bd) {
            unsigned int me = eq[j], c = 0;
            for (unsigned int t = 0; t < ne; t++) if (eq[t] <= me) c++;
            if (c == extra) s_cut = me;
        }
        __syncthreads();
    }
    if (threadIdx.x == 0) { g_thr[b] = thr; g_cut[b] = s_cut; }
}

// ============================== WRITE ======================================

__global__ void __launch_bounds__(512) k_write(const float4* __restrict__ in,
                                               float4* __restrict__ out, int nvec) {
    const int b = blockIdx.y;
    const unsigned int thrk = g_thr[b];
    const unsigned int cut  = g_cut[b];
    const float4* p = in  + (size_t)b * nvec;
    float4*       q = out + (size_t)b * nvec;
    const int bd = blockDim.x;
    // reverse chunk order: start where passA's L2 footprint is freshest
    const int chunk = gridDim.x - 1 - blockIdx.x;
    int per_block = (nvec + gridDim.x - 1) / gridDim.x;
    int start = chunk * per_block;
    int end   = min(start + per_block, nvec);

    if (thrk > 0x80000000u) {
        const unsigned int tbits = thrk ^ 0x80000000u;
        const float tf = __uint_as_float(tbits);
        int i = start + threadIdx.x;
        for (; i + 3 * bd < end; i += 4 * bd) {
            float4 v0 = p[i];
            float4 v1 = p[i + bd];
            float4 v2 = p[i + 2 * bd];
            float4 v3 = p[i + 3 * bd];
            float4 o0, o1, o2, o3;
            unsigned int g0 = (unsigned int)i * 4u;
            unsigned int g1 = (unsigned int)(i + bd) * 4u;
            unsigned int g2 = (unsigned int)(i + 2 * bd) * 4u;
            unsigned int g3 = (unsigned int)(i + 3 * bd) * 4u;
            #define MSK(x, gi) ((x) > tf || (__float_as_uint(x) == tbits && (gi) <= cut)) ? (x) : 0.0f
            o0.x = MSK(v0.x, g0+0u); o0.y = MSK(v0.y, g0+1u); o0.z = MSK(v0.z, g0+2u); o0.w = MSK(v0.w, g0+3u);
            o1.x = MSK(v1.x, g1+0u); o1.y = MSK(v1.y, g1+1u); o1.z = MSK(v1.z, g1+2u); o1.w = MSK(v1.w, g1+3u);
            o2.x = MSK(v2.x, g2+0u); o2.y = MSK(v2.y, g2+1u); o2.z = MSK(v2.z, g2+2u); o2.w = MSK(v2.w, g2+3u);
            o3.x = MSK(v3.x, g3+0u); o3.y = MSK(v3.y, g3+1u); o3.z = MSK(v3.z, g3+2u); o3.w = MSK(v3.w, g3+3u);
            __stcs(&q[i], o0);
            __stcs(&q[i + bd], o1);
            __stcs(&q[i + 2 * bd], o2);
            __stcs(&q[i + 3 * bd], o3);
        }
        for (; i < end; i += bd) {
            float4 v = p[i];
            unsigned int g0 = (unsigned int)i * 4u;
            float4 o;
            o.x = MSK(v.x, g0+0u); o.y = MSK(v.y, g0+1u); o.z = MSK(v.z, g0+2u); o.w = MSK(v.w, g0+3u);
            __stcs(&q[i], o);
            #undef MSK
        }
    } else {
        for (int i = start + threadIdx.x; i < end; i += bd) {
            float4 v = p[i];
            unsigned int base = (unsigned int)i * 4u;
            unsigned int k0 = f2k(v.x), k1 = f2k(v.y), k2 = f2k(v.z), k3 = f2k(v.w);
            float4 o;
            o.x = (k0 > thrk || (k0 == thrk && base + 0u <= cut)) ? v.x : 0.0f;
            o.y = (k1 > thrk || (k1 == thrk && base + 1u <= cut)) ? v.y : 0.0f;
            o.z = (k2 > thrk || (k2 == thrk && base + 2u <= cut)) ? v.z : 0.0f;
            o.w = (k3 > thrk || (k3 == thrk && base + 3u <= cut)) ? v.w : 0.0f;
            __stcs(&q[i], o);
        }
    }
    // reset scratch for next graph replay
    if (blockIdx.x == 0 && blockIdx.y == 0) {
        if (threadIdx.x < NBATCH) {
            g_cnt[threadIdx.x] = 0;
            g_gt[threadIdx.x] = 0;
            g_arrive[threadIdx.x] = 0;
        }
        if (threadIdx.x == 0) g_fail = 0;
    }
}

// ============================== HOST =======================================

extern "C" void kernel_launch(void* const* d_in, const int* in_sizes, int n_in,
                              void* d_out, int out_size) {
    (void)n_in; (void)out_size;
    const int total = in_sizes[0];           // 33,554,432
    const int N     = total / NBATCH;        // 4,194,304
    int k = (int)((double)N * 0.1);          // 419,430
    if (k < 1) k = 1;
    const int nvec = N / 4;                  // 1,048,576 float4 per row

    const float4* in  = (const float4*)d_in[0];
    float4*       out = (float4*)d_out;

    dim3 gA(128, NBATCH);
    dim3 gW(256, NBATCH);

    k_passA<<<gA, 512>>>(in, nvec, k);
    fb_all <<<NBATCH, 1024>>>(in, nvec, k);
    k_write<<<gW, 512>>>(in, out, nvec);
}

// round 12
// speedup vs baseline: 2.0445x; 1.1666x over previous
#include <cuda_runtime.h>
#include <stdint.h>

// ---------------------------------------------------------------------------
// LateralInhibition: per-batch top-k masking (B=8, N=4,194,304, k=419,430).
//
// Single-read structure (256MB total traffic instead of 384MB):
//   passAW: read 128MB + write 128MB fused. out[i] = (x > HI ? x : 0);
//           counts x>=LO; stages window candidates (LO<=x<=HI, ~14.7K/row).
//           Last block per row (arrive-counter) runs exact select on the
//           L2-hot candidates: fine hist -> threshold + tie cutoff.
//   fb_all: gated on g_fail; fully-general exact select. ~1us early-exit.
//   k_fix : fast path: scatter-write the ~14.7K/row kept candidates
//           (key >= thr with tie cutoff) over the zeros passAW left.
//           fallback path (g_fail): full general masked rewrite.
//           Arrive-counter reset of all scratch for next graph replay.
// ---------------------------------------------------------------------------

#define NBATCH 8
#define FBBINS 8192
#define CAP    262144
#define SCAP   1024
#define FINE   1024
#define MCAP   512
#define LO_F   1.272f       // window: ~+-12 sigma around thr ~ 1.2816+-0.00084
#define HI_F   1.292f

__device__ unsigned int g_cnt [NBATCH];     // window candidates per row
__device__ unsigned int g_gt  [NBATCH];     // count of x >= LO per row
__device__ unsigned int g_arrive[NBATCH];
__device__ unsigned int g_fix_arr;
__device__ unsigned int g_ckey[NBATCH][CAP];
__device__ unsigned int g_cidx[NBATCH][CAP];
__device__ unsigned int g_thr [NBATCH];     // f2k key of threshold
__device__ unsigned int g_cut [NBATCH];     // max included idx among ties
__device__ int          g_fail;

// monotonic float -> uint key (larger float => larger key)
__device__ __forceinline__ unsigned int f2k(float f) {
    unsigned int u = __float_as_uint(f);
    return u ^ (0x80000000u | (unsigned int)((int)u >> 31));
}

// ======================= PASS A + WRITE + SELECT ===========================

__global__ void __launch_bounds__(512, 3)
k_passAW(const float4* __restrict__ in, float4* __restrict__ out,
         int nvec, int k) {
    __shared__ unsigned int skey[SCAP], sidx[SCAP];   // staging; reused by select
    __shared__ unsigned int s_n, s_base, s_gt, s_last;
    __shared__ unsigned int s_bsel, s_r, s_m, s_thr, s_extra, s_E, s_neq, s_cut;
    __shared__ unsigned int csum[32];
    const int b   = blockIdx.y;
    const int bd  = blockDim.x;
    const int tid = threadIdx.x;
    if (tid == 0) { s_n = 0; s_gt = 0; }
    __syncthreads();

    const float4* p = in  + (size_t)b * nvec;
    float4*       q = out + (size_t)b * nvec;
    int per_block = (nvec + gridDim.x - 1) / gridDim.x;
    int start = blockIdx.x * per_block;
    int end   = min(start + per_block, nvec);
    unsigned int mygt = 0;

    const unsigned int LOB = __float_as_uint(LO_F);
    const unsigned int WID = __float_as_uint(HI_F) - LOB;   // window width (bits)
    const unsigned int GTW = 0x7F800000u - LOB;             // [LO, +inf] width
    // t = bits(x)-LOB:  t<=GTW <=> x in [LO,+inf] (negatives/NaN wrap huge);
    //                   t<=WID <=> x in [LO,HI]   (window; candidate push).
    // Output now: keep x iff x > HI (certainly top-k since hi < k);
    // zero otherwise (window elems fixed up later by k_fix).
    // hi = gt - n = count(x > HI) exactly.

    #define PA_VEC(v, vi) do {                                               \
        unsigned int t0 = __float_as_uint((v).x) - LOB;                      \
        unsigned int t1 = __float_as_uint((v).y) - LOB;                      \
        unsigned int t2 = __float_as_uint((v).z) - LOB;                      \
        unsigned int t3 = __float_as_uint((v).w) - LOB;                      \
        mygt += (t0 <= GTW) ? 1u : 0u;                                       \
        mygt += (t1 <= GTW) ? 1u : 0u;                                       \
        mygt += (t2 <= GTW) ? 1u : 0u;                                       \
        mygt += (t3 <= GTW) ? 1u : 0u;                                       \
        float4 o;                                                            \
        o.x = ((v).x > HI_F) ? (v).x : 0.0f;                                 \
        o.y = ((v).y > HI_F) ? (v).y : 0.0f;                                 \
        o.z = ((v).z > HI_F) ? (v).z : 0.0f;                                 \
        o.w = ((v).w > HI_F) ? (v).w : 0.0f;                                 \
        __stcs(&q[vi], o);                                                   \
        unsigned int mm = umin(umin(t0, t1), umin(t2, t3));                  \
        if (mm <= WID) {                                                     \
            unsigned int gb = (unsigned int)(vi) * 4u;                       \
            if (t0 <= WID) { unsigned int _p = atomicAdd(&s_n, 1u);          \
                if (_p < SCAP) { skey[_p] = t0 + LOB; sidx[_p] = gb; } }     \
            if (t1 <= WID) { unsigned int _p = atomicAdd(&s_n, 1u);          \
                if (_p < SCAP) { skey[_p] = t1 + LOB; sidx[_p] = gb + 1u; } }\
            if (t2 <= WID) { unsigned int _p = atomicAdd(&s_n, 1u);          \
                if (_p < SCAP) { skey[_p] = t2 + LOB; sidx[_p] = gb + 2u; } }\
            if (t3 <= WID) { unsigned int _p = atomicAdd(&s_n, 1u);          \
                if (_p < SCAP) { skey[_p] = t3 + LOB; sidx[_p] = gb + 3u; } }\
        }                                                                    \
    } while (0)

    int i = start + tid;
    for (; i + 3 * bd < end; i += 4 * bd) {
        float4 v0 = p[i];
        float4 v1 = p[i + bd];
        float4 v2 = p[i + 2 * bd];
        float4 v3 = p[i + 3 * bd];
        PA_VEC(v0, i);
        PA_VEC(v1, i + bd);
        PA_VEC(v2, i + 2 * bd);
        PA_VEC(v3, i + 3 * bd);
    }
    for (; i < end; i += bd) {
        float4 v = p[i];
        PA_VEC(v, i);
    }
    #undef PA_VEC

    #pragma unroll
    for (int o = 16; o > 0; o >>= 1) mygt += __shfl_down_sync(0xFFFFFFFFu, mygt, o);
    if ((tid & 31) == 0) atomicAdd(&s_gt, mygt);
    __syncthreads();
    if (tid == 0) {
        if (s_n > SCAP) g_fail = 1;          // staging overflow -> fallback
        unsigned int m = min(s_n, (unsigned int)SCAP);
        atomicAdd(&g_gt[b], s_gt);
        s_base = atomicAdd(&g_cnt[b], m);
        s_n = m;
    }
    __syncthreads();
    for (unsigned int j = tid; j < s_n; j += bd) {
        unsigned int gp = s_base + j;
        if (gp < CAP) { g_ckey[b][gp] = skey[j]; g_cidx[b][gp] = sidx[j]; }
    }
    __syncthreads();
    __threadfence();
    if (tid == 0)
        s_last = (atomicAdd(&g_arrive[b], 1u) == gridDim.x - 1u) ? 1u : 0u;
    __syncthreads();
    if (!s_last) return;

    // ================= last block of this row: exact select ================
    __threadfence();
    const unsigned int n  = g_cnt[b];
    const unsigned int gt = g_gt[b];
    const unsigned int uk = (unsigned int)k;
    // hi = gt - n (count strictly above window). valid window position:
    //   hi < k  <=> gt - n < k ;  hi + n >= k  <=> gt >= k
    if (!((n <= CAP) && (n <= gt) && (gt - n < uk) && (gt >= uk))) {
        if (tid == 0) g_fail = 1;
        return;
    }
    const unsigned int rank = uk - (gt - n);   // 1-based rank within window
    const unsigned int LOB2 = __float_as_uint(LO_F);
    unsigned int* h   = skey;    // reuse staging smem: h[FINE]
    unsigned int* aux = sidx;    // reuse: boundary keys / eq indices

    for (int j = tid; j < FINE; j += bd) h[j] = 0;
    if (tid == 0) { s_m = 0; s_neq = 0; s_cut = 0xFFFFFFFFu; s_thr = 0; s_extra = 0; s_E = 0; }
    __syncthreads();
    // fine bins: window bit-span ~0x2A000; >>8 = 256-ulp bins, <=672 <= FINE.
    for (unsigned int j = tid; j < n; j += bd)
        atomicAdd(&h[(g_ckey[b][j] - LOB2) >> 8], 1u);
    __syncthreads();
    if (tid < 32) {
        unsigned int s = 0;
        #pragma unroll
        for (int t = 0; t < 32; t++) s += h[tid * 32 + t];
        csum[tid] = s;
    }
    __syncthreads();
    if (tid == 0) {
        unsigned int cum = 0;
        int c = 31;
        for (; c > 0; c--) {
            if (cum + csum[c] >= rank) break;
            cum += csum[c];
        }
        int bsel = c * 32;
        for (int d = c * 32 + 31; d >= c * 32; d--) {
            if (cum + h[d] >= rank) { bsel = d; break; }
            cum += h[d];
        }
        s_bsel = (unsigned int)bsel;
        s_r    = rank - cum;
    }
    __syncthreads();
    const unsigned int bsel = s_bsel, r = s_r;
    for (unsigned int j = tid; j < n; j += bd) {
        unsigned int uv = g_ckey[b][j];
        if (((uv - LOB2) >> 8) == bsel) {
            unsigned int pp = atomicAdd(&s_m, 1u);
            if (pp < MCAP) aux[pp] = uv;
        }
    }
    __syncthreads();
    unsigned int m = s_m;
    if (m > MCAP) { if (tid == 0) g_fail = 1; return; }
    for (unsigned int j = tid; j < m; j += bd) {
        unsigned int x = aux[j], cg = 0, ce = 0;
        for (unsigned int t = 0; t < m; t++) {
            unsigned int y = aux[t];
            cg += (y > x); ce += (y == x);
        }
        if (cg < r && r <= cg + ce) { s_thr = x; s_extra = r - cg; s_E = ce; }
    }
    __syncthreads();
    const unsigned int thr = s_thr, extra = s_extra, E = s_E;
    if (extra < E) {   // tie-break: extra-th smallest index among equals
        for (unsigned int j = tid; j < n; j += bd) {
            if (g_ckey[b][j] == thr) {
                unsigned int pp = atomicAdd(&s_neq, 1u);
                if (pp < SCAP) aux[pp] = g_cidx[b][j];
            }
        }
        __syncthreads();
        unsigned int ne = s_neq;
        if (ne > SCAP) { if (tid == 0) g_fail = 1; return; }
        for (unsigned int j = tid; j < ne; j += bd) {
            unsigned int me = aux[j], c2 = 0;
            for (unsigned int t = 0; t < ne; t++) c2 += (aux[t] <= me);
            if (c2 == extra) s_cut = me;
        }
        __syncthreads();
    }
    if (tid == 0) {
        g_thr[b] = thr | 0x80000000u;   // f2k of a positive float
        g_cut[b] = s_cut;
    }
}

// ================== FALLBACK: one kernel, fully general ====================

__global__ void __launch_bounds__(1024) fb_all(const float4* __restrict__ in,
                                               int nvec, int k) {
    if (!g_fail) return;
    __shared__ unsigned int sh[FBBINS];
    __shared__ unsigned int s_pref, s_krem, s_n;
    __shared__ unsigned int s_fixedval, s_fixedmask, s_rank, s_E, s_neq, s_cut;
    const int b = blockIdx.x;
    const float4* p = in + (size_t)b * nvec;
    const int bd = blockDim.x;

    for (int i = threadIdx.x; i < FBBINS; i += bd) sh[i] = 0;
    __syncthreads();
    for (int i = threadIdx.x; i < nvec; i += bd) {
        float4 v = p[i];
        atomicAdd(&sh[f2k(v.x) >> 19], 1u);
        atomicAdd(&sh[f2k(v.y) >> 19], 1u);
        atomicAdd(&sh[f2k(v.z) >> 19], 1u);
        atomicAdd(&sh[f2k(v.w) >> 19], 1u);
    }
    __syncthreads();
    if (threadIdx.x == 0) {
        unsigned int cum = 0;
        for (int j = FBBINS - 1; j >= 0; j--) {
            unsigned int c = sh[j];
            if (cum + c >= (unsigned int)k) { s_pref = (unsigned int)j; s_krem = (unsigned int)k - cum; break; }
            cum += c;
        }
        s_n = 0;
    }
    __syncthreads();
    const unsigned int pref = s_pref;
    for (int i = threadIdx.x; i < nvec; i += bd) {
        float4 v = p[i];
        unsigned int kk[4] = { f2k(v.x), f2k(v.y), f2k(v.z), f2k(v.w) };
        #pragma unroll
        for (int j = 0; j < 4; j++) {
            if ((kk[j] >> 19) == pref) {
                unsigned int pos = atomicAdd(&s_n, 1u);
                if (pos < CAP) {
                    g_ckey[b][pos] = kk[j];
                    g_cidx[b][pos] = (unsigned int)i * 4u + (unsigned int)j;
                }
            }
        }
    }
    __syncthreads();
    const unsigned int n = min(s_n, (unsigned int)CAP);
    if (threadIdx.x == 0) {
        s_fixedval = 0; s_fixedmask = 0; s_rank = s_krem; s_E = 0;
        s_neq = 0; s_cut = 0xFFFFFFFFu;
    }
    __syncthreads();
    const int shifts[3] = { 11, 3, 0 };
    const int widths[3] = { 8, 8, 3 };
    for (int r = 0; r < 3; r++) {
        const int s = shifts[r];
        const unsigned int mw = (1u << widths[r]) - 1u;
        for (int i = threadIdx.x; i < 256; i += bd) sh[i] = 0;
        __syncthreads();
        const unsigned int fm = s_fixedmask, fv = s_fixedval;
        for (unsigned int i = threadIdx.x; i < n; i += bd) {
            unsigned int low = g_ckey[b][i] & 0x7FFFFu;
            if ((low & fm) == fv) atomicAdd(&sh[(low >> s) & mw], 1u);
        }
        __syncthreads();
        if (threadIdx.x == 0) {
            unsigned int cum = 0, rank = s_rank, sel = 0;
            for (int d = (int)mw; d >= 0; d--) {
                unsigned int c = sh[d];
                if (cum + c >= rank) { sel = (unsigned int)d; s_rank = rank - cum; s_E = c; break; }
                cum += c;
            }
            s_fixedval  |= sel << s;
            s_fixedmask |= mw  << s;
        }
        __syncthreads();
    }
    const unsigned int thr   = (pref << 19) | s_fixedval;
    const unsigned int extra = s_rank;
    const unsigned int E     = s_E;
    __syncthreads();
    if (extra < E) {
        unsigned int* eq = sh;
        for (unsigned int i = threadIdx.x; i < n; i += bd) {
            if (g_ckey[b][i] == thr) {
                unsigned int pos = atomicAdd(&s_neq, 1u);
                if (pos < FBBINS) eq[pos] = g_cidx[b][i];
            }
        }
        __syncthreads();
        unsigned int ne = min(s_neq, (unsigned int)FBBINS);
        for (unsigned int j = threadIdx.x; j < ne; j += bd) {
            unsigned int me = eq[j], c = 0;
            for (unsigned int t = 0; t < ne; t++) if (eq[t] <= me) c++;
            if (c == extra) s_cut = me;
        }
        __syncthreads();
    }
    if (threadIdx.x == 0) { g_thr[b] = thr; g_cut[b] = s_cut; }
}

// ======================== FIXUP (+ fallback write, reset) ==================

__global__ void __launch_bounds__(1024) k_fix(const float4* __restrict__ in,
                                              float* __restrict__ outf,
                                              int nvec) {
    __shared__ unsigned int s_last;
    const int b  = blockIdx.x;
    const int bd = blockDim.x;
    const int tid = threadIdx.x;
    const int fail = g_fail;   // every block reads BEFORE any block can reset

    if (!fail) {
        // fast path: flip kept window candidates from 0 to their value
        const unsigned int n   = min(g_cnt[b], (unsigned int)CAP);
        const unsigned int thr = g_thr[b];
        const unsigned int cut = g_cut[b];
        float* orow = outf + (size_t)b * nvec * 4;
        for (unsigned int j = tid; j < n; j += bd) {
            unsigned int key = g_ckey[b][j];
            unsigned int kf  = key | 0x80000000u;   // f2k of positive float
            unsigned int idx = g_cidx[b][j];
            if (kf > thr || (kf == thr && idx <= cut))
                orow[idx] = __uint_as_float(key);
        }
    } else {
        // fallback: full general masked rewrite of this row (perf-irrelevant)
        const unsigned int thr = g_thr[b];
        const unsigned int cut = g_cut[b];
        const float4* p = in + (size_t)b * nvec;
        float4* q = (float4*)(outf + (size_t)b * nvec * 4);
        for (int i = tid; i < nvec; i += bd) {
            float4 v = p[i];
            unsigned int base = (unsigned int)i * 4u;
            unsigned int k0 = f2k(v.x), k1 = f2k(v.y), k2 = f2k(v.z), k3 = f2k(v.w);
            float4 o;
            o.x = (k0 > thr || (k0 == thr && base + 0u <= cut)) ? v.x : 0.0f;
            o.y = (k1 > thr || (k1 == thr && base + 1u <= cut)) ? v.y : 0.0f;
            o.z = (k2 > thr || (k2 == thr && base + 2u <= cut)) ? v.z : 0.0f;
            o.w = (k3 > thr || (k3 == thr && base + 3u <= cut)) ? v.w : 0.0f;
            q[i] = o;
        }
    }

    // arrive-counter reset: only the LAST block (all blocks have already read
    // g_fail and finished their work) clears scratch for the next replay.
    __threadfence();
    __syncthreads();
    if (tid == 0)
        s_last = (atomicAdd(&g_fix_arr, 1u) == gridDim.x - 1u) ? 1u : 0u;
    __syncthreads();
    if (s_last) {
        if (tid < NBATCH) {
            g_cnt[tid] = 0;
            g_gt[tid] = 0;
            g_arrive[tid] = 0;
        }
        if (tid == 0) { g_fail = 0; g_fix_arr = 0; }
    }
}

// ============================== HOST =======================================

extern "C" void kernel_launch(void* const* d_in, const int* in_sizes, int n_in,
                              void* d_out, int out_size) {
    (void)n_in; (void)out_size;
    const int total = in_sizes[0];           // 33,554,432
    const int N     = total / NBATCH;        // 4,194,304
    int k = (int)((double)N * 0.1);          // 419,430
    if (k < 1) k = 1;
    const int nvec = N / 4;                  // 1,048,576 float4 per row

    const float4* in  = (const float4*)d_in[0];
    float4*       out = (float4*)d_out;

    dim3 gA(256, NBATCH);

    k_passAW<<<gA, 512>>>(in, out, nvec, k);
    fb_all  <<<NBATCH, 1024>>>(in, nvec, k);
    k_fix   <<<NBATCH, 1024>>>(in, (float*)out, nvec);
}

// round 14
// speedup vs baseline: 2.0747x; 1.0148x over previous
#include <cuda_runtime.h>
#include <stdint.h>

// ---------------------------------------------------------------------------
// LateralInhibition: per-batch top-k masking (B=8, N=4,194,304, k=419,430).
//
// 2 launches:
//   passAW: read 128MB + write 128MB fused, out[i] = (x > HI ? x : 0);
//           counts x>=LO; stages window candidates (LO<=x<=HI, ~14.7K/row).
//           Last block per row (arrive-counter): exact select on L2-hot
//           candidates AND scatter-fixup of kept candidates AND row-counter
//           reset (with barrier between counter loads and reset — the R13
//           race). Entire fast path in one kernel.
//   fb    : gated on g_fail; fully-general exact select + full rewrite +
//           g_fail reset. <1us early-exit on the fast path.
// ---------------------------------------------------------------------------

#define NBATCH 8
#define FBBINS 8192
#define CAP    262144
#define SCAP   1024
#define FINE   1024
#define MCAP   512
#define LO_F   1.272f       // window: ~+-12 sigma around thr ~ 1.2816+-0.00084
#define HI_F   1.292f

__device__ unsigned int g_cnt [NBATCH];     // window candidates per row
__device__ unsigned int g_gt  [NBATCH];     // count of x >= LO per row
__device__ unsigned int g_arrive[NBATCH];
__device__ unsigned int g_fb_arr;
__device__ unsigned int g_ckey[NBATCH][CAP];
__device__ unsigned int g_cidx[NBATCH][CAP];
__device__ int          g_fail;

// monotonic float -> uint key (larger float => larger key)
__device__ __forceinline__ unsigned int f2k(float f) {
    unsigned int u = __float_as_uint(f);
    return u ^ (0x80000000u | (unsigned int)((int)u >> 31));
}

// ================ PASS A + WRITE + SELECT + FIXUP (fast path) ==============

__global__ void __launch_bounds__(512, 3)
k_passAW(const float4* __restrict__ in, float4* __restrict__ out,
         int nvec, int k) {
    __shared__ unsigned int skey[SCAP], sidx[SCAP];   // staging; reused by select
    __shared__ unsigned int s_n, s_base, s_gt, s_last;
    __shared__ unsigned int s_bsel, s_r, s_m, s_thr, s_extra, s_E, s_neq, s_cut;
    __shared__ unsigned int csum[32];
    const int b   = blockIdx.y;
    const int bd  = blockDim.x;
    const int tid = threadIdx.x;
    if (tid == 0) { s_n = 0; s_gt = 0; }
    __syncthreads();

    const float4* p = in  + (size_t)b * nvec;
    float4*       q = out + (size_t)b * nvec;
    int per_block = (nvec + gridDim.x - 1) / gridDim.x;
    int start = blockIdx.x * per_block;
    int end   = min(start + per_block, nvec);
    unsigned int mygt = 0;

    const unsigned int LOB = __float_as_uint(LO_F);
    const unsigned int WID = __float_as_uint(HI_F) - LOB;   // window width (bits)
    const unsigned int GTW = 0x7F800000u - LOB;             // [LO, +inf] width
    // t = bits(x)-LOB:  t<=GTW <=> x in [LO,+inf] (negatives/NaN wrap huge);
    //                   t<=WID <=> x in [LO,HI]   (window; candidate push).
    // out now: keep x iff x > HI (certainly top-k since count(x>HI) < k);
    // zero otherwise (window elems fixed up by the last block's scatter).
    // hi = gt - n = count(x > HI) exactly.

    #define PA_VEC(v, vi) do {                                               \
        unsigned int t0 = __float_as_uint((v).x) - LOB;                      \
        unsigned int t1 = __float_as_uint((v).y) - LOB;                      \
        unsigned int t2 = __float_as_uint((v).z) - LOB;                      \
        unsigned int t3 = __float_as_uint((v).w) - LOB;                      \
        mygt += (t0 <= GTW) ? 1u : 0u;                                       \
        mygt += (t1 <= GTW) ? 1u : 0u;                                       \
        mygt += (t2 <= GTW) ? 1u : 0u;                                       \
        mygt += (t3 <= GTW) ? 1u : 0u;                                       \
        float4 o;                                                            \
        o.x = ((v).x > HI_F) ? (v).x : 0.0f;                                 \
        o.y = ((v).y > HI_F) ? (v).y : 0.0f;                                 \
        o.z = ((v).z > HI_F) ? (v).z : 0.0f;                                 \
        o.w = ((v).w > HI_F) ? (v).w : 0.0f;                                 \
        __stcs(&q[vi], o);                                                   \
        unsigned int mm = umin(umin(t0, t1), umin(t2, t3));                  \
        if (mm <= WID) {                                                     \
            unsigned int gb = (unsigned int)(vi) * 4u;                       \
            if (t0 <= WID) { unsigned int _p = atomicAdd(&s_n, 1u);          \
                if (_p < SCAP) { skey[_p] = t0 + LOB; sidx[_p] = gb; } }     \
            if (t1 <= WID) { unsigned int _p = atomicAdd(&s_n, 1u);          \
                if (_p < SCAP) { skey[_p] = t1 + LOB; sidx[_p] = gb + 1u; } }\
            if (t2 <= WID) { unsigned int _p = atomicAdd(&s_n, 1u);          \
                if (_p < SCAP) { skey[_p] = t2 + LOB; sidx[_p] = gb + 2u; } }\
            if (t3 <= WID) { unsigned int _p = atomicAdd(&s_n, 1u);          \
                if (_p < SCAP) { skey[_p] = t3 + LOB; sidx[_p] = gb + 3u; } }\
        }                                                                    \
    } while (0)

    int i = start + tid;
    for (; i + 3 * bd < end; i += 4 * bd) {
        float4 v0 = p[i];
        float4 v1 = p[i + bd];
        float4 v2 = p[i + 2 * bd];
        float4 v3 = p[i + 3 * bd];
        PA_VEC(v0, i);
        PA_VEC(v1, i + bd);
        PA_VEC(v2, i + 2 * bd);
        PA_VEC(v3, i + 3 * bd);
    }
    for (; i < end; i += bd) {
        float4 v = p[i];
        PA_VEC(v, i);
    }
    #undef PA_VEC

    #pragma unroll
    for (int o = 16; o > 0; o >>= 1) mygt += __shfl_down_sync(0xFFFFFFFFu, mygt, o);
    if ((tid & 31) == 0) atomicAdd(&s_gt, mygt);
    __syncthreads();
    if (tid == 0) {
        if (s_n > SCAP) g_fail = 1;          // staging overflow -> fallback
        unsigned int m = min(s_n, (unsigned int)SCAP);
        atomicAdd(&g_gt[b], s_gt);
        s_base = atomicAdd(&g_cnt[b], m);
        s_n = m;
    }
    __syncthreads();
    for (unsigned int j = tid; j < s_n; j += bd) {
        unsigned int gp = s_base + j;
        if (gp < CAP) { g_ckey[b][gp] = skey[j]; g_cidx[b][gp] = sidx[j]; }
    }
    __syncthreads();
    __threadfence();
    if (tid == 0)
        s_last = (atomicAdd(&g_arrive[b], 1u) == gridDim.x - 1u) ? 1u : 0u;
    __syncthreads();
    if (!s_last) return;

    // ========== last block of this row: select + fixup + reset =============
    __threadfence();
    const unsigned int ncnt = g_cnt[b];
    const unsigned int gt   = g_gt[b];
    const unsigned int uk   = (unsigned int)k;
    __syncthreads();   // ALL threads have loaded the counters (R13 bug fix)
    // counters captured by every thread -> reset row state for next replay
    if (tid == 0) { g_cnt[b] = 0; g_gt[b] = 0; g_arrive[b] = 0; }
    // hi = gt - n (count strictly above window). valid window position:
    //   hi < k  <=> gt - n < k ;  hi + n >= k  <=> gt >= k
    if (!((ncnt <= CAP) && (ncnt <= gt) && (gt - ncnt < uk) && (gt >= uk))) {
        if (tid == 0) g_fail = 1;
        return;
    }
    const unsigned int n    = ncnt;
    const unsigned int rank = uk - (gt - n);   // 1-based rank within window
    const unsigned int LOB2 = __float_as_uint(LO_F);
    unsigned int* h   = skey;    // reuse staging smem: h[FINE]
    unsigned int* aux = sidx;    // reuse: boundary keys / eq indices

    for (int j = tid; j < FINE; j += bd) h[j] = 0;
    if (tid == 0) { s_m = 0; s_neq = 0; s_cut = 0xFFFFFFFFu; s_thr = 0; s_extra = 0; s_E = 0; }
    __syncthreads();
    // fine bins: window bit-span ~0x2A000; >>8 = 256-ulp bins, <=672 <= FINE.
    for (unsigned int j = tid; j < n; j += bd)
        atomicAdd(&h[(g_ckey[b][j] - LOB2) >> 8], 1u);
    __syncthreads();
    if (tid < 32) {
        unsigned int s = 0;
        #pragma unroll
        for (int t = 0; t < 32; t++) s += h[tid * 32 + t];
        csum[tid] = s;
    }
    __syncthreads();
    if (tid == 0) {
        unsigned int cum = 0;
        int c = 31;
        for (; c > 0; c--) {
            if (cum + csum[c] >= rank) break;
            cum += csum[c];
        }
        int bsel = c * 32;
        for (int d = c * 32 + 31; d >= c * 32; d--) {
            if (cum + h[d] >= rank) { bsel = d; break; }
            cum += h[d];
        }
        s_bsel = (unsigned int)bsel;
        s_r    = rank - cum;
    }
    __syncthreads();
    const unsigned int bsel = s_bsel, r = s_r;
    for (unsigned int j = tid; j < n; j += bd) {
        unsigned int uv = g_ckey[b][j];
        if (((uv - LOB2) >> 8) == bsel) {
            unsigned int pp = atomicAdd(&s_m, 1u);
            if (pp < MCAP) aux[pp] = uv;
        }
    }
    __syncthreads();
    unsigned int m = s_m;
    if (m > MCAP) { if (tid == 0) g_fail = 1; return; }
    for (unsigned int j = tid; j < m; j += bd) {
        unsigned int x = aux[j], cg = 0, ce = 0;
        for (unsigned int t = 0; t < m; t++) {
            unsigned int y = aux[t];
            cg += (y > x); ce += (y == x);
        }
        if (cg < r && r <= cg + ce) { s_thr = x; s_extra = r - cg; s_E = ce; }
    }
    __syncthreads();
    const unsigned int thr = s_thr, extra = s_extra, E = s_E;
    if (extra < E) {   // tie-break: extra-th smallest index among equals
        for (unsigned int j = tid; j < n; j += bd) {
            if (g_ckey[b][j] == thr) {
                unsigned int pp = atomicAdd(&s_neq, 1u);
                if (pp < SCAP) aux[pp] = g_cidx[b][j];
            }
        }
        __syncthreads();
        unsigned int ne = s_neq;
        if (ne > SCAP) { if (tid == 0) g_fail = 1; return; }
        for (unsigned int j = tid; j < ne; j += bd) {
            unsigned int me = aux[j], c2 = 0;
            for (unsigned int t = 0; t < ne; t++) c2 += (aux[t] <= me);
            if (c2 == extra) s_cut = me;
        }
        __syncthreads();
    }

    // scatter-fixup: flip kept window candidates from 0 to their value.
    // If ANY row overflowed staging, g_fail is set and the fallback kernel
    // fully rewrites out[] -- a stray fast-path scatter is harmless.
    if (g_fail) return;
    const unsigned int thrk = thr | 0x80000000u;   // f2k of positive float
    const unsigned int cut  = s_cut;
    float* orow = (float*)q;
    for (unsigned int j = tid; j < n; j += bd) {
        unsigned int key = g_ckey[b][j];
        unsigned int kf  = key | 0x80000000u;
        unsigned int idx = g_cidx[b][j];
        if (kf > thrk || (kf == thrk && idx <= cut))
            orow[idx] = __uint_as_float(key);
    }
}

// ============ FALLBACK: fully-general select + rewrite (gated) =============

__global__ void __launch_bounds__(1024) k_fb(const float4* __restrict__ in,
                                             float4* __restrict__ out,
                                             int nvec, int k) {
    if (!g_fail) return;
    __shared__ unsigned int sh[FBBINS];
    __shared__ unsigned int s_pref, s_krem, s_n, s_last;
    __shared__ unsigned int s_fixedval, s_fixedmask, s_rank, s_E, s_neq, s_cut;
    const int b = blockIdx.x;
    const float4* p = in + (size_t)b * nvec;
    const int bd = blockDim.x;

    for (int i = threadIdx.x; i < FBBINS; i += bd) sh[i] = 0;
    __syncthreads();
    for (int i = threadIdx.x; i < nvec; i += bd) {
        float4 v = p[i];
        atomicAdd(&sh[f2k(v.x) >> 19], 1u);
        atomicAdd(&sh[f2k(v.y) >> 19], 1u);
        atomicAdd(&sh[f2k(v.z) >> 19], 1u);
        atomicAdd(&sh[f2k(v.w) >> 19], 1u);
    }
    __syncthreads();
    if (threadIdx.x == 0) {
        unsigned int cum = 0;
        for (int j = FBBINS - 1; j >= 0; j--) {
            unsigned int c = sh[j];
            if (cum + c >= (unsigned int)k) { s_pref = (unsigned int)j; s_krem = (unsigned int)k - cum; break; }
            cum += c;
        }
        s_n = 0;
    }
    __syncthreads();
    const unsigned int pref = s_pref;
    for (int i = threadIdx.x; i < nvec; i += bd) {
        float4 v = p[i];
        unsigned int kk[4] = { f2k(v.x), f2k(v.y), f2k(v.z), f2k(v.w) };
        #pragma unroll
        for (int j = 0; j < 4; j++) {
            if ((kk[j] >> 19) == pref) {
                unsigned int pos = atomicAdd(&s_n, 1u);
                if (pos < CAP) {
                    g_ckey[b][pos] = kk[j];
                    g_cidx[b][pos] = (unsigned int)i * 4u + (unsigned int)j;
                }
            }
        }
    }
    __syncthreads();
    const unsigned int n = min(s_n, (unsigned int)CAP);
    if (threadIdx.x == 0) {
        s_fixedval = 0; s_fixedmask = 0; s_rank = s_krem; s_E = 0;
        s_neq = 0; s_cut = 0xFFFFFFFFu;
    }
    __syncthreads();
    const int shifts[3] = { 11, 3, 0 };
    const int widths[3] = { 8, 8, 3 };
    for (int r = 0; r < 3; r++) {
        const int s = shifts[r];
        const unsigned int mw = (1u << widths[r]) - 1u;
        for (int i = threadIdx.x; i < 256; i += bd) sh[i] = 0;
        __syncthreads();
        const unsigned int fm = s_fixedmask, fv = s_fixedval;
        for (unsigned int i = threadIdx.x; i < n; i += bd) {
            unsigned int low = g_ckey[b][i] & 0x7FFFFu;
            if ((low & fm) == fv) atomicAdd(&sh[(low >> s) & mw], 1u);
        }
        __syncthreads();
        if (threadIdx.x == 0) {
            unsigned int cum = 0, rank = s_rank, sel = 0;
            for (int d = (int)mw; d >= 0; d--) {
                unsigned int c = sh[d];
                if (cum + c >= rank) { sel = (unsigned int)d; s_rank = rank - cum; s_E = c; break; }
                cum += c;
            }
            s_fixedval  |= sel << s;
            s_fixedmask |= mw  << s;
        }
        __syncthreads();
    }
    const unsigned int thr   = (pref << 19) | s_fixedval;
    const unsigned int extra = s_rank;
    const unsigned int E     = s_E;
    __syncthreads();
    if (extra < E) {
        unsigned int* eq = sh;
        for (unsigned int i = threadIdx.x; i < n; i += bd) {
            if (g_ckey[b][i] == thr) {
                unsigned int pos = atomicAdd(&s_neq, 1u);
                if (pos < FBBINS) eq[pos] = g_cidx[b][i];
            }
        }
        __syncthreads();
        unsigned int ne = min(s_neq, (unsigned int)FBBINS);
        for (unsigned int j = threadIdx.x; j < ne; j += bd) {
            unsigned int me = eq[j], c = 0;
            for (unsigned int t = 0; t < ne; t++) if (eq[t] <= me) c++;
            if (c == extra) s_cut = me;
        }
        __syncthreads();
    }
    const unsigned int cut = s_cut;

    // full rewrite of this row (overrides anything the fast path produced)
    float4* q = out + (size_t)b * nvec;
    for (int i = threadIdx.x; i < nvec; i += bd) {
        float4 v = p[i];
        unsigned int base = (unsigned int)i * 4u;
        unsigned int k0 = f2k(v.x), k1 = f2k(v.y), k2 = f2k(v.z), k3 = f2k(v.w);
        float4 o;
        o.x = (k0 > thr || (k0 == thr && base + 0u <= cut)) ? v.x : 0.0f;
        o.y = (k1 > thr || (k1 == thr && base + 1u <= cut)) ? v.y : 0.0f;
        o.z = (k2 > thr || (k2 == thr && base + 2u <= cut)) ? v.z : 0.0f;
        o.w = (k3 > thr || (k3 == thr && base + 3u <= cut)) ? v.w : 0.0f;
        q[i] = o;
    }

    // reset g_fail once all fallback blocks are done
    __threadfence();
    __syncthreads();
    if (threadIdx.x == 0)
        s_last = (atomicAdd(&g_fb_arr, 1u) == gridDim.x - 1u) ? 1u : 0u;
    __syncthreads();
    if (s_last && threadIdx.x == 0) { g_fail = 0; g_fb_arr = 0; }
}

// ============================== HOST =======================================

extern "C" void kernel_launch(void* const* d_in, const int* in_sizes, int n_in,
                              void* d_out, int out_size) {
    (void)n_in; (void)out_size;
    const int total = in_sizes[0];           // 33,554,432
    const int N     = total / NBATCH;        // 4,194,304
    int k = (int)((double)N * 0.1);          // 419,430
    if (k < 1) k = 1;
    const int nvec = N / 4;                  // 1,048,576 float4 per row

    const float4* in  = (const float4*)d_in[0];
    float4*       out = (float4*)d_out;

    dim3 gA(256, NBATCH);

    k_passAW<<<gA, 512>>>(in, out, nvec, k);
    k_fb    <<<NBATCH, 1024>>>(in, out, nvec, k);
}